// round 4
// baseline (speedup 1.0000x reference)
#include <cuda_runtime.h>
#include <math.h>

// Problem constants (fixed by the reference)
#define BB 16
#define NN 1024
#define CC 768
#define HH 12
#define HD 64

// Scratch (device globals: allocation-free per harness rules)
// g_qkv layout: [3][B][H][N][HD]
__device__ float g_qkv[(size_t)3 * BB * HH * NN * HD];
// g_att layout: [B][N][C]
__device__ float g_att[(size_t)BB * NN * CC];

// ---------------------------------------------------------------------------
// Tiled SGEMM: C[M, Ncols] = A[M, K] @ Bm[Ncols, K]^T  (both row-major)
// 64x64 block, BK=16, 256 threads, 4x4 micro-tile per thread.
// MODE 0: A = x, scatter output into g_qkv [3][B][H][N][HD]
// MODE 1: A = g_att, output = acc + bias -> Cout (row-major [M, Ncols])
// ---------------------------------------------------------------------------
template <int MODE>
__global__ __launch_bounds__(256) void sgemm_kernel(
    const float* __restrict__ A, const float* __restrict__ Bm,
    const float* __restrict__ bias, float* __restrict__ Cout,
    int M, int Ncols, int K)
{
    __shared__ float As[64][17];
    __shared__ float Bs[64][17];

    const float* Ap = (MODE == 1) ? (const float*)g_att : A;

    const int t  = threadIdx.x;
    const int tx = t & 15;       // 0..15  -> output col group
    const int ty = t >> 4;       // 0..15  -> output row group
    const int m0 = blockIdx.y * 64;
    const int n0 = blockIdx.x * 64;

    const int lr = t >> 2;          // 0..63 tile row for loads
    const int lk = (t & 3) << 2;    // 0,4,8,12 k offset (float4)
    const float* Arow = Ap + (size_t)(m0 + lr) * K + lk;
    const float* Brow = Bm + (size_t)(n0 + lr) * K + lk;

    float acc[4][4];
#pragma unroll
    for (int i = 0; i < 4; ++i)
#pragma unroll
        for (int j = 0; j < 4; ++j) acc[i][j] = 0.f;

    for (int k0 = 0; k0 < K; k0 += 16) {
        float4 av = *(const float4*)(Arow + k0);
        float4 bv = *(const float4*)(Brow + k0);
        As[lr][lk + 0] = av.x; As[lr][lk + 1] = av.y;
        As[lr][lk + 2] = av.z; As[lr][lk + 3] = av.w;
        Bs[lr][lk + 0] = bv.x; Bs[lr][lk + 1] = bv.y;
        Bs[lr][lk + 2] = bv.z; Bs[lr][lk + 3] = bv.w;
        __syncthreads();

#pragma unroll
        for (int kk = 0; kk < 16; ++kk) {
            float a0 = As[ty * 4 + 0][kk];
            float a1 = As[ty * 4 + 1][kk];
            float a2 = As[ty * 4 + 2][kk];
            float a3 = As[ty * 4 + 3][kk];
            float b0 = Bs[tx + 0][kk];
            float b1 = Bs[tx + 16][kk];
            float b2 = Bs[tx + 32][kk];
            float b3 = Bs[tx + 48][kk];
            acc[0][0] += a0 * b0; acc[0][1] += a0 * b1; acc[0][2] += a0 * b2; acc[0][3] += a0 * b3;
            acc[1][0] += a1 * b0; acc[1][1] += a1 * b1; acc[1][2] += a1 * b2; acc[1][3] += a1 * b3;
            acc[2][0] += a2 * b0; acc[2][1] += a2 * b1; acc[2][2] += a2 * b2; acc[2][3] += a2 * b3;
            acc[3][0] += a3 * b0; acc[3][1] += a3 * b1; acc[3][2] += a3 * b2; acc[3][3] += a3 * b3;
        }
        __syncthreads();
    }

    if (MODE == 0) {
        // scatter into g_qkv: col j -> (s, h, d); row m -> (b, n)
#pragma unroll
        for (int ii = 0; ii < 4; ++ii) {
            int m = m0 + ty * 4 + ii;
            int b = m >> 10;
            int n = m & 1023;
#pragma unroll
            for (int jj = 0; jj < 4; ++jj) {
                int j = n0 + tx + 16 * jj;
                int s = j / CC;
                int r = j - s * CC;
                int h = r >> 6;
                int d = r & 63;
                g_qkv[((((size_t)s * BB + b) * HH + h) * NN + n) * HD + d] = acc[ii][jj];
            }
        }
    } else {
#pragma unroll
        for (int ii = 0; ii < 4; ++ii) {
            int m = m0 + ty * 4 + ii;
#pragma unroll
            for (int jj = 0; jj < 4; ++jj) {
                int j = n0 + tx + 16 * jj;
                Cout[(size_t)m * Ncols + j] = acc[ii][jj] + bias[j];
            }
        }
    }
}

// ---------------------------------------------------------------------------
// Attention kernel: one block per (q-tile of 32 rows, b*H + h).
// Computes S = Q Kt (32x1024) into SMEM, policy softmax, then P @ V.
// 256 threads. Dynamic SMEM:
//   S   : 32*1024          = 32768 floats
//   KV  : 128*65 (>=64*129)=  8320 floats (K transposed stride 129 / V stride 65)
//   Qs  : 32*65            =  2080 floats
//   POL : 1024             =  1024 floats
//   RSM : 32               =    32 floats
// ---------------------------------------------------------------------------
#define SMEM_ATTN_FLOATS (32 * 1024 + 8320 + 2080 + 1024 + 32)
#define SMEM_ATTN_BYTES  (SMEM_ATTN_FLOATS * 4)

__global__ __launch_bounds__(256) void attn_kernel(const float* __restrict__ policy)
{
    extern __shared__ float sm[];
    float* S   = sm;                 // 32*1024
    float* KV  = S + 32 * 1024;      // 8320
    float* Qs  = KV + 8320;          // 2080
    float* POL = Qs + 2080;          // 1024
    float* RSM = POL + 1024;         // 32

    const int qt = blockIdx.x;       // 0..31
    const int bh = blockIdx.y;       // 0..191
    const int b  = bh / HH;
    const int h  = bh - b * HH;
    const int t  = threadIdx.x;
    const int tx = t & 31;
    const int ty = t >> 5;
    const float scale = 0.125f;      // hd^-0.5, hd=64

    const size_t plane = (size_t)NN * HD;
    const float* Qg = g_qkv + ((size_t)(0 * BB + b) * HH + h) * plane + (size_t)qt * 32 * HD;
    const float* Kg = g_qkv + ((size_t)(1 * BB + b) * HH + h) * plane;
    const float* Vg = g_qkv + ((size_t)(2 * BB + b) * HH + h) * plane;

    // load policy row and Q tile
    for (int j = t; j < NN; j += 256) POL[j] = policy[b * NN + j];
    for (int e = t; e < 32 * 16; e += 256) {
        int i  = e >> 4;
        int c4 = (e & 15) << 2;
        float4 v = *(const float4*)(Qg + i * HD + c4);
        Qs[i * 65 + c4 + 0] = v.x;
        Qs[i * 65 + c4 + 1] = v.y;
        Qs[i * 65 + c4 + 2] = v.z;
        Qs[i * 65 + c4 + 3] = v.w;
    }

    // ---- S = Q @ K^T over 8 key tiles of 128 ----
    for (int kt = 0; kt < 8; ++kt) {
        const float* Kt = Kg + kt * 128 * HD;
        for (int e = t; e < 128 * 64; e += 256) {
            int j = e >> 6, d = e & 63;
            KV[d * 129 + j] = Kt[j * HD + d];    // transposed, stride 129 (conflict-free)
        }
        __syncthreads();

        float acc[4][4] = {};
#pragma unroll
        for (int d = 0; d < 64; ++d) {
            float q0 = Qs[(ty * 4 + 0) * 65 + d];
            float q1 = Qs[(ty * 4 + 1) * 65 + d];
            float q2 = Qs[(ty * 4 + 2) * 65 + d];
            float q3 = Qs[(ty * 4 + 3) * 65 + d];
            float k0 = KV[d * 129 + tx + 0];
            float k1 = KV[d * 129 + tx + 32];
            float k2 = KV[d * 129 + tx + 64];
            float k3 = KV[d * 129 + tx + 96];
            acc[0][0] += q0 * k0; acc[0][1] += q0 * k1; acc[0][2] += q0 * k2; acc[0][3] += q0 * k3;
            acc[1][0] += q1 * k0; acc[1][1] += q1 * k1; acc[1][2] += q1 * k2; acc[1][3] += q1 * k3;
            acc[2][0] += q2 * k0; acc[2][1] += q2 * k1; acc[2][2] += q2 * k2; acc[2][3] += q2 * k3;
            acc[3][0] += q3 * k0; acc[3][1] += q3 * k1; acc[3][2] += q3 * k2; acc[3][3] += q3 * k3;
        }
#pragma unroll
        for (int ii = 0; ii < 4; ++ii)
#pragma unroll
            for (int jj = 0; jj < 4; ++jj)
                S[(ty * 4 + ii) * NN + kt * 128 + tx + 32 * jj] = acc[ii][jj];
        __syncthreads();
    }

    // ---- policy softmax over each of the 32 rows (one warp handles 4 rows) ----
    for (int r = ty; r < 32; r += 8) {
        float m = -1e30f;
        for (int j = tx; j < NN; j += 32) m = fmaxf(m, S[r * NN + j]);
#pragma unroll
        for (int o = 16; o; o >>= 1) m = fmaxf(m, __shfl_xor_sync(0xffffffffu, m, o));

        const int gi = qt * 32 + r;   // global query index (diagonal of policy eye)
        float sum = 0.f;
        for (int j = tx; j < NN; j += 32) {
            float pw = (j == gi) ? 1.0f : POL[j];
            float p  = __expf((S[r * NN + j] - m) * scale) * pw;
            sum += p;
            S[r * NN + j] = p + (1e-6f / 1024.0f);   // fold +eps/N into P
        }
#pragma unroll
        for (int o = 16; o; o >>= 1) sum += __shfl_xor_sync(0xffffffffu, sum, o);
        if (tx == 0) RSM[r] = sum + 1e-6f;
    }
    __syncthreads();

    // ---- O = P @ V over 8 value tiles of 128 ----
    float o[4][2] = {};
    for (int vt = 0; vt < 8; ++vt) {
        const float* Vt = Vg + vt * 128 * HD;
        for (int e = t; e < 128 * 64; e += 256) {
            int j = e >> 6, d = e & 63;
            KV[j * 65 + d] = Vt[j * HD + d];
        }
        __syncthreads();

#pragma unroll 4
        for (int j = 0; j < 128; ++j) {
            float p0 = S[(ty * 4 + 0) * NN + vt * 128 + j];
            float p1 = S[(ty * 4 + 1) * NN + vt * 128 + j];
            float p2 = S[(ty * 4 + 2) * NN + vt * 128 + j];
            float p3 = S[(ty * 4 + 3) * NN + vt * 128 + j];
            float v0 = KV[j * 65 + tx + 0];
            float v1 = KV[j * 65 + tx + 32];
            o[0][0] += p0 * v0; o[0][1] += p0 * v1;
            o[1][0] += p1 * v0; o[1][1] += p1 * v1;
            o[2][0] += p2 * v0; o[2][1] += p2 * v1;
            o[3][0] += p3 * v0; o[3][1] += p3 * v1;
        }
        __syncthreads();
    }

    // epilogue: divide by (rowsum + eps), write to g_att [B][N][C]
#pragma unroll
    for (int ii = 0; ii < 4; ++ii) {
        int i = ty * 4 + ii;
        float inv = 1.0f / RSM[i];
        int gi = qt * 32 + i;
        float* dst = g_att + ((size_t)b * NN + gi) * CC + h * HD;
        dst[tx + 0]  = o[ii][0] * inv;
        dst[tx + 32] = o[ii][1] * inv;
    }
}

// ---------------------------------------------------------------------------
// Launch
// ---------------------------------------------------------------------------
extern "C" void kernel_launch(void* const* d_in, const int* in_sizes, int n_in,
                              void* d_out, int out_size)
{
    const float* x      = (const float*)d_in[0];   // [16, 1024, 768]
    const float* policy = (const float*)d_in[1];   // [16, 1024, 1]
    const float* w_qkv  = (const float*)d_in[2];   // [2304, 768]
    const float* w_proj = (const float*)d_in[3];   // [768, 768]
    const float* b_proj = (const float*)d_in[4];   // [768]
    float* out = (float*)d_out;                    // [16, 1024, 768]

    (void)in_sizes; (void)n_in; (void)out_size;

    cudaFuncSetAttribute(attn_kernel, cudaFuncAttributeMaxDynamicSharedMemorySize,
                         SMEM_ATTN_BYTES);

    // QKV GEMM: [16384, 768] @ [2304, 768]^T -> scatter to g_qkv
    {
        dim3 grid(2304 / 64, 16384 / 64);
        sgemm_kernel<0><<<grid, 256>>>(x, w_qkv, nullptr, nullptr, 16384, 2304, 768);
    }

    // Attention: grid (32 q-tiles, 192 head-batches)
    {
        dim3 grid(32, BB * HH);
        attn_kernel<<<grid, 256, SMEM_ATTN_BYTES>>>(policy);
    }

    // Projection: g_att [16384,768] @ w_proj^T + bias -> out
    {
        dim3 grid(768 / 64, 16384 / 64);
        sgemm_kernel<1><<<grid, 256>>>(nullptr, w_proj, b_proj, out, 16384, 768, 768);
    }
}

// round 6
// speedup vs baseline: 1.1872x; 1.1872x over previous
#include <cuda_runtime.h>
#include <cuda_bf16.h>
#include <cstdint>
#include <math.h>

// Problem constants
#define BB 16
#define NN 1024
#define CC 768
#define HH 12
#define HD 64

// Scratch
__device__ float g_qkv[(size_t)3 * BB * HH * NN * HD];  // [3][B][H][N][HD]
__device__ float g_att[(size_t)BB * NN * CC];           // [B][N][C]

// ===========================================================================
// Helpers (all plain sm_80+ PTX — no 'a'-suffix features)
// ===========================================================================
__device__ __forceinline__ uint32_t smem_u32(const void* p) {
    uint32_t a;
    asm("{ .reg .u64 t; cvta.to.shared.u64 t, %1; cvt.u32.u64 %0, t; }"
        : "=r"(a) : "l"(p));
    return a;
}

__device__ __forceinline__ void ldm_x4(uint32_t& r0, uint32_t& r1,
                                       uint32_t& r2, uint32_t& r3, uint32_t addr) {
    asm volatile("ldmatrix.sync.aligned.m8n8.x4.shared.b16 {%0,%1,%2,%3}, [%4];"
                 : "=r"(r0), "=r"(r1), "=r"(r2), "=r"(r3) : "r"(addr));
}

__device__ __forceinline__ void mma_bf16(float* c, const uint32_t* a,
                                         uint32_t b0, uint32_t b1) {
    asm volatile(
        "mma.sync.aligned.m16n8k16.row.col.f32.bf16.bf16.f32 "
        "{%0,%1,%2,%3}, {%4,%5,%6,%7}, {%8,%9}, {%0,%1,%2,%3};"
        : "+f"(c[0]), "+f"(c[1]), "+f"(c[2]), "+f"(c[3])
        : "r"(a[0]), "r"(a[1]), "r"(a[2]), "r"(a[3]), "r"(b0), "r"(b1));
}

__device__ __forceinline__ uint32_t pack_bf(__nv_bfloat16 a, __nv_bfloat16 b) {
    uint32_t ua = (uint32_t)__bfloat16_as_ushort(a);
    uint32_t ub = (uint32_t)__bfloat16_as_ushort(b);
    return ua | (ub << 16);
}

// ===========================================================================
// bf16 mma.sync GEMM (3-term split): C[M,Ncols] = A[M,K] @ W[Ncols,K]^T
// Block tile 128x128, BK=32, 256 threads (8 warps, each 64x32).
// MODE 0: A = x, scatter -> g_qkv. MODE 1: A = g_att, +bias -> Cout.
// ===========================================================================
#define BM 128
#define BN 128
#define BK 32
#define STR 40   // smem row stride in bf16 elements (80B: 16B-aligned, conflict-free)

template <int MODE>
__global__ __launch_bounds__(256) void tc_gemm(
    const float* __restrict__ A, const float* __restrict__ W,
    const float* __restrict__ bias, float* __restrict__ Cout, int K)
{
    __shared__ __nv_bfloat16 Ah[BM * STR];
    __shared__ __nv_bfloat16 Al[BM * STR];
    __shared__ __nv_bfloat16 Bh[BN * STR];
    __shared__ __nv_bfloat16 Bl[BN * STR];

    const float* Ap = (MODE == 1) ? (const float*)g_att : A;

    const int t    = threadIdx.x;
    const int wid  = t >> 5;
    const int lane = t & 31;
    const int m0   = blockIdx.y * BM;
    const int n0   = blockIdx.x * BN;

    // warp tile: 2 warp-rows (64 m) x 4 warp-cols (32 n)
    const int warp_m = (wid & 1) * 64;
    const int warp_n = (wid >> 1) * 32;

    // ldmatrix addressing components
    const int rsel = lane & 15;         // row within 16-row fragment
    const int ksel = (lane >> 4) * 8;   // k element offset (0 or 8)

    const uint32_t sAh = smem_u32(Ah);
    const uint32_t sAl = smem_u32(Al);
    const uint32_t sBh = smem_u32(Bh);
    const uint32_t sBl = smem_u32(Bl);

    float acc[4][4][4];
#pragma unroll
    for (int i = 0; i < 4; ++i)
#pragma unroll
        for (int j = 0; j < 4; ++j)
#pragma unroll
            for (int k = 0; k < 4; ++k) acc[i][j][k] = 0.f;

    const int nchunks = K / BK;   // 24
    for (int ck = 0; ck < nchunks; ++ck) {
        const int k0 = ck * BK;

        // ---- load + split A tile (128x32 floats = 1024 float4) ----
#pragma unroll
        for (int i = 0; i < 4; ++i) {
            int idx = t + 256 * i;
            int r = idx >> 3, c = (idx & 7) * 4;
            float4 v = *(const float4*)(Ap + (size_t)(m0 + r) * K + k0 + c);
            __nv_bfloat16 h0 = __float2bfloat16(v.x);
            __nv_bfloat16 h1 = __float2bfloat16(v.y);
            __nv_bfloat16 h2 = __float2bfloat16(v.z);
            __nv_bfloat16 h3 = __float2bfloat16(v.w);
            __nv_bfloat16 l0 = __float2bfloat16(v.x - __bfloat162float(h0));
            __nv_bfloat16 l1 = __float2bfloat16(v.y - __bfloat162float(h1));
            __nv_bfloat16 l2 = __float2bfloat16(v.z - __bfloat162float(h2));
            __nv_bfloat16 l3 = __float2bfloat16(v.w - __bfloat162float(h3));
            int off = r * STR + c;
            *(uint2*)(Ah + off) = make_uint2(pack_bf(h0, h1), pack_bf(h2, h3));
            *(uint2*)(Al + off) = make_uint2(pack_bf(l0, l1), pack_bf(l2, l3));
        }
        // ---- load + split B tile (128x32 floats) ----
#pragma unroll
        for (int i = 0; i < 4; ++i) {
            int idx = t + 256 * i;
            int r = idx >> 3, c = (idx & 7) * 4;
            float4 v = *(const float4*)(W + (size_t)(n0 + r) * K + k0 + c);
            __nv_bfloat16 h0 = __float2bfloat16(v.x);
            __nv_bfloat16 h1 = __float2bfloat16(v.y);
            __nv_bfloat16 h2 = __float2bfloat16(v.z);
            __nv_bfloat16 h3 = __float2bfloat16(v.w);
            __nv_bfloat16 l0 = __float2bfloat16(v.x - __bfloat162float(h0));
            __nv_bfloat16 l1 = __float2bfloat16(v.y - __bfloat162float(h1));
            __nv_bfloat16 l2 = __float2bfloat16(v.z - __bfloat162float(h2));
            __nv_bfloat16 l3 = __float2bfloat16(v.w - __bfloat162float(h3));
            int off = r * STR + c;
            *(uint2*)(Bh + off) = make_uint2(pack_bf(h0, h1), pack_bf(h2, h3));
            *(uint2*)(Bl + off) = make_uint2(pack_bf(l0, l1), pack_bf(l2, l3));
        }
        __syncthreads();

        // ---- 2 k16 steps per chunk ----
#pragma unroll
        for (int ks = 0; ks < 2; ++ks) {
            const int kb = ks * 16 + ksel;

            // B fragments (hi & lo): 2 x ldmatrix.x4 each (16 n-rows)
            uint32_t bh[2][4], bl[2][4];
#pragma unroll
            for (int ntt = 0; ntt < 2; ++ntt) {
                uint32_t boff = ((warp_n + ntt * 16 + rsel) * STR + kb) * 2;
                ldm_x4(bh[ntt][0], bh[ntt][1], bh[ntt][2], bh[ntt][3], sBh + boff);
                ldm_x4(bl[ntt][0], bl[ntt][1], bl[ntt][2], bl[ntt][3], sBl + boff);
            }

#pragma unroll
            for (int mt = 0; mt < 4; ++mt) {
                uint32_t aoff = ((warp_m + mt * 16 + rsel) * STR + kb) * 2;
                uint32_t ah[4], al[4];
                ldm_x4(ah[0], ah[1], ah[2], ah[3], sAh + aoff);
                ldm_x4(al[0], al[1], al[2], al[3], sAl + aoff);
#pragma unroll
                for (int nt = 0; nt < 4; ++nt) {
                    uint32_t b0h = bh[nt >> 1][nt & 1];
                    uint32_t b1h = bh[nt >> 1][2 + (nt & 1)];
                    uint32_t b0l = bl[nt >> 1][nt & 1];
                    uint32_t b1l = bl[nt >> 1][2 + (nt & 1)];
                    mma_bf16(acc[mt][nt], ah, b0h, b1h);   // hi*hi
                    mma_bf16(acc[mt][nt], ah, b0l, b1l);   // hi*lo
                    mma_bf16(acc[mt][nt], al, b0h, b1h);   // lo*hi
                }
            }
        }
        __syncthreads();
    }

    // ---- epilogue: direct fragment stores (float2) ----
    const int cr = lane >> 2;           // row within m16
    const int cc = (lane & 3) * 2;      // col within n8 (even)
#pragma unroll
    for (int mt = 0; mt < 4; ++mt) {
#pragma unroll
        for (int nt = 0; nt < 4; ++nt) {
            int jr = n0 + warp_n + nt * 8 + cc;
#pragma unroll
            for (int half = 0; half < 2; ++half) {
                int m = m0 + warp_m + mt * 16 + cr + half * 8;
                float e0 = acc[mt][nt][half * 2 + 0];
                float e1 = acc[mt][nt][half * 2 + 1];
                if (MODE == 0) {
                    int b = m >> 10, n = m & 1023;
                    int s = jr / CC;
                    int rr = jr - s * CC;
                    int h = rr >> 6, d = rr & 63;
                    float* dst = &g_qkv[((((size_t)s * BB + b) * HH + h) * NN + n) * HD + d];
                    *(float2*)dst = make_float2(e0, e1);
                } else {
                    float2 bv = *(const float2*)(bias + jr);
                    float* dst = &Cout[(size_t)m * CC + jr];
                    *(float2*)dst = make_float2(e0 + bv.x, e1 + bv.y);
                }
            }
        }
    }
}

// ===========================================================================
// Attention kernel (unchanged, known-good fp32)
// ===========================================================================
#define SMEM_ATTN_FLOATS (32 * 1024 + 8320 + 2080 + 1024 + 32)
#define SMEM_ATTN_BYTES  (SMEM_ATTN_FLOATS * 4)

__global__ __launch_bounds__(256) void attn_kernel(const float* __restrict__ policy)
{
    extern __shared__ float sm[];
    float* S   = sm;
    float* KV  = S + 32 * 1024;
    float* Qs  = KV + 8320;
    float* POL = Qs + 2080;
    float* RSM = POL + 1024;

    const int qt = blockIdx.x;
    const int bh = blockIdx.y;
    const int b  = bh / HH;
    const int h  = bh - b * HH;
    const int t  = threadIdx.x;
    const int tx = t & 31;
    const int ty = t >> 5;
    const float scale = 0.125f;

    const size_t plane = (size_t)NN * HD;
    const float* Qg = g_qkv + ((size_t)(0 * BB + b) * HH + h) * plane + (size_t)qt * 32 * HD;
    const float* Kg = g_qkv + ((size_t)(1 * BB + b) * HH + h) * plane;
    const float* Vg = g_qkv + ((size_t)(2 * BB + b) * HH + h) * plane;

    for (int j = t; j < NN; j += 256) POL[j] = policy[b * NN + j];
    for (int e = t; e < 32 * 16; e += 256) {
        int i  = e >> 4;
        int c4 = (e & 15) << 2;
        float4 v = *(const float4*)(Qg + i * HD + c4);
        Qs[i * 65 + c4 + 0] = v.x;
        Qs[i * 65 + c4 + 1] = v.y;
        Qs[i * 65 + c4 + 2] = v.z;
        Qs[i * 65 + c4 + 3] = v.w;
    }

    for (int kt = 0; kt < 8; ++kt) {
        const float* Kt = Kg + kt * 128 * HD;
        for (int e = t; e < 128 * 64; e += 256) {
            int j = e >> 6, d = e & 63;
            KV[d * 129 + j] = Kt[j * HD + d];
        }
        __syncthreads();

        float acc[4][4] = {};
#pragma unroll
        for (int d = 0; d < 64; ++d) {
            float q0 = Qs[(ty * 4 + 0) * 65 + d];
            float q1 = Qs[(ty * 4 + 1) * 65 + d];
            float q2 = Qs[(ty * 4 + 2) * 65 + d];
            float q3 = Qs[(ty * 4 + 3) * 65 + d];
            float k0 = KV[d * 129 + tx + 0];
            float k1 = KV[d * 129 + tx + 32];
            float k2 = KV[d * 129 + tx + 64];
            float k3 = KV[d * 129 + tx + 96];
            acc[0][0] += q0 * k0; acc[0][1] += q0 * k1; acc[0][2] += q0 * k2; acc[0][3] += q0 * k3;
            acc[1][0] += q1 * k0; acc[1][1] += q1 * k1; acc[1][2] += q1 * k2; acc[1][3] += q1 * k3;
            acc[2][0] += q2 * k0; acc[2][1] += q2 * k1; acc[2][2] += q2 * k2; acc[2][3] += q2 * k3;
            acc[3][0] += q3 * k0; acc[3][1] += q3 * k1; acc[3][2] += q3 * k2; acc[3][3] += q3 * k3;
        }
#pragma unroll
        for (int ii = 0; ii < 4; ++ii)
#pragma unroll
            for (int jj = 0; jj < 4; ++jj)
                S[(ty * 4 + ii) * NN + kt * 128 + tx + 32 * jj] = acc[ii][jj];
        __syncthreads();
    }

    for (int r = ty; r < 32; r += 8) {
        float m = -1e30f;
        for (int j = tx; j < NN; j += 32) m = fmaxf(m, S[r * NN + j]);
#pragma unroll
        for (int o = 16; o; o >>= 1) m = fmaxf(m, __shfl_xor_sync(0xffffffffu, m, o));

        const int gi = qt * 32 + r;
        float sum = 0.f;
        for (int j = tx; j < NN; j += 32) {
            float pw = (j == gi) ? 1.0f : POL[j];
            float p  = __expf((S[r * NN + j] - m) * scale) * pw;
            sum += p;
            S[r * NN + j] = p + (1e-6f / 1024.0f);
        }
#pragma unroll
        for (int o = 16; o; o >>= 1) sum += __shfl_xor_sync(0xffffffffu, sum, o);
        if (tx == 0) RSM[r] = sum + 1e-6f;
    }
    __syncthreads();

    float o[4][2] = {};
    for (int vt = 0; vt < 8; ++vt) {
        const float* Vt = Vg + vt * 128 * HD;
        for (int e = t; e < 128 * 64; e += 256) {
            int j = e >> 6, d = e & 63;
            KV[j * 65 + d] = Vt[j * HD + d];
        }
        __syncthreads();

#pragma unroll 4
        for (int j = 0; j < 128; ++j) {
            float p0 = S[(ty * 4 + 0) * NN + vt * 128 + j];
            float p1 = S[(ty * 4 + 1) * NN + vt * 128 + j];
            float p2 = S[(ty * 4 + 2) * NN + vt * 128 + j];
            float p3 = S[(ty * 4 + 3) * NN + vt * 128 + j];
            float v0 = KV[j * 65 + tx + 0];
            float v1 = KV[j * 65 + tx + 32];
            o[0][0] += p0 * v0; o[0][1] += p0 * v1;
            o[1][0] += p1 * v0; o[1][1] += p1 * v1;
            o[2][0] += p2 * v0; o[2][1] += p2 * v1;
            o[3][0] += p3 * v0; o[3][1] += p3 * v1;
        }
        __syncthreads();
    }

#pragma unroll
    for (int ii = 0; ii < 4; ++ii) {
        int i = ty * 4 + ii;
        float inv = 1.0f / RSM[i];
        int gi = qt * 32 + i;
        float* dst = g_att + ((size_t)b * NN + gi) * CC + h * HD;
        dst[tx + 0]  = o[ii][0] * inv;
        dst[tx + 32] = o[ii][1] * inv;
    }
}

// ===========================================================================
// Launch
// ===========================================================================
extern "C" void kernel_launch(void* const* d_in, const int* in_sizes, int n_in,
                              void* d_out, int out_size)
{
    const float* x      = (const float*)d_in[0];   // [16, 1024, 768]
    const float* policy = (const float*)d_in[1];   // [16, 1024, 1]
    const float* w_qkv  = (const float*)d_in[2];   // [2304, 768]
    const float* w_proj = (const float*)d_in[3];   // [768, 768]
    const float* b_proj = (const float*)d_in[4];   // [768]
    float* out = (float*)d_out;                    // [16, 1024, 768]

    (void)in_sizes; (void)n_in; (void)out_size;

    cudaFuncSetAttribute(attn_kernel, cudaFuncAttributeMaxDynamicSharedMemorySize,
                         SMEM_ATTN_BYTES);

    // QKV GEMM: [16384,768] @ [2304,768]^T -> g_qkv (mma.sync bf16 3x-split)
    {
        dim3 grid(2304 / BN, 16384 / BM);   // (18, 128)
        tc_gemm<0><<<grid, 256>>>(x, w_qkv, nullptr, nullptr, CC);
    }
    // Attention
    {
        dim3 grid(32, BB * HH);
        attn_kernel<<<grid, 256, SMEM_ATTN_BYTES>>>(policy);
    }
    // Projection: g_att @ w_proj^T + bias -> out
    {
        dim3 grid(CC / BN, 16384 / BM);     // (6, 128)
        tc_gemm<1><<<grid, 256>>>(nullptr, w_proj, b_proj, out, CC);
    }
}

// round 7
// speedup vs baseline: 3.1259x; 2.6330x over previous
#include <cuda_runtime.h>
#include <cuda_bf16.h>
#include <cstdint>
#include <math.h>

// Problem constants
#define BB 16
#define NN 1024
#define CC 768
#define HH 12
#define HD 64

// Scratch
__device__ float g_qkv[(size_t)3 * BB * HH * NN * HD];  // [3][B][H][N][HD]
__device__ float g_att[(size_t)BB * NN * CC];           // [B][N][C]

// ===========================================================================
// Helpers (plain sm_80+ PTX — safe for compute_103 virtual arch)
// ===========================================================================
__device__ __forceinline__ uint32_t smem_u32(const void* p) {
    uint32_t a;
    asm("{ .reg .u64 t; cvta.to.shared.u64 t, %1; cvt.u32.u64 %0, t; }"
        : "=r"(a) : "l"(p));
    return a;
}

__device__ __forceinline__ void ldm_x4(uint32_t& r0, uint32_t& r1,
                                       uint32_t& r2, uint32_t& r3, uint32_t addr) {
    asm volatile("ldmatrix.sync.aligned.m8n8.x4.shared.b16 {%0,%1,%2,%3}, [%4];"
                 : "=r"(r0), "=r"(r1), "=r"(r2), "=r"(r3) : "r"(addr));
}

__device__ __forceinline__ void mma_bf16(float* c, const uint32_t* a,
                                         uint32_t b0, uint32_t b1) {
    asm volatile(
        "mma.sync.aligned.m16n8k16.row.col.f32.bf16.bf16.f32 "
        "{%0,%1,%2,%3}, {%4,%5,%6,%7}, {%8,%9}, {%0,%1,%2,%3};"
        : "+f"(c[0]), "+f"(c[1]), "+f"(c[2]), "+f"(c[3])
        : "r"(a[0]), "r"(a[1]), "r"(a[2]), "r"(a[3]), "r"(b0), "r"(b1));
}

__device__ __forceinline__ uint32_t pack_bf(__nv_bfloat16 a, __nv_bfloat16 b) {
    uint32_t ua = (uint32_t)__bfloat16_as_ushort(a);
    uint32_t ub = (uint32_t)__bfloat16_as_ushort(b);
    return ua | (ub << 16);
}

// split a float into bf16 hi + bf16 lo (residual)
__device__ __forceinline__ void bf_split(float x, __nv_bfloat16& h, __nv_bfloat16& l) {
    h = __float2bfloat16(x);
    l = __float2bfloat16(x - __bfloat162float(h));
}

// ===========================================================================
// bf16 mma.sync GEMM (3-term split): C[M,Ncols] = A[M,K] @ W[Ncols,K]^T
// Block tile 128x128, BK=32, 256 threads (8 warps, each 64x32).
// MODE 0: A = x, scatter -> g_qkv. MODE 1: A = g_att, +bias -> Cout.
// ===========================================================================
#define BM 128
#define BN 128
#define BK 32
#define STR 40

template <int MODE>
__global__ __launch_bounds__(256) void tc_gemm(
    const float* __restrict__ A, const float* __restrict__ W,
    const float* __restrict__ bias, float* __restrict__ Cout, int K)
{
    __shared__ __nv_bfloat16 Ah[BM * STR];
    __shared__ __nv_bfloat16 Al[BM * STR];
    __shared__ __nv_bfloat16 Bh[BN * STR];
    __shared__ __nv_bfloat16 Bl[BN * STR];

    const float* Ap = (MODE == 1) ? (const float*)g_att : A;

    const int t    = threadIdx.x;
    const int wid  = t >> 5;
    const int lane = t & 31;
    const int m0   = blockIdx.y * BM;
    const int n0   = blockIdx.x * BN;

    const int warp_m = (wid & 1) * 64;
    const int warp_n = (wid >> 1) * 32;
    const int rsel = lane & 15;
    const int ksel = (lane >> 4) * 8;

    const uint32_t sAh = smem_u32(Ah);
    const uint32_t sAl = smem_u32(Al);
    const uint32_t sBh = smem_u32(Bh);
    const uint32_t sBl = smem_u32(Bl);

    float acc[4][4][4];
#pragma unroll
    for (int i = 0; i < 4; ++i)
#pragma unroll
        for (int j = 0; j < 4; ++j)
#pragma unroll
            for (int k = 0; k < 4; ++k) acc[i][j][k] = 0.f;

    const int nchunks = K / BK;
    for (int ck = 0; ck < nchunks; ++ck) {
        const int k0 = ck * BK;

#pragma unroll
        for (int i = 0; i < 4; ++i) {
            int idx = t + 256 * i;
            int r = idx >> 3, c = (idx & 7) * 4;
            float4 v = *(const float4*)(Ap + (size_t)(m0 + r) * K + k0 + c);
            __nv_bfloat16 h0, h1, h2, h3, l0, l1, l2, l3;
            bf_split(v.x, h0, l0); bf_split(v.y, h1, l1);
            bf_split(v.z, h2, l2); bf_split(v.w, h3, l3);
            int off = r * STR + c;
            *(uint2*)(Ah + off) = make_uint2(pack_bf(h0, h1), pack_bf(h2, h3));
            *(uint2*)(Al + off) = make_uint2(pack_bf(l0, l1), pack_bf(l2, l3));
        }
#pragma unroll
        for (int i = 0; i < 4; ++i) {
            int idx = t + 256 * i;
            int r = idx >> 3, c = (idx & 7) * 4;
            float4 v = *(const float4*)(W + (size_t)(n0 + r) * K + k0 + c);
            __nv_bfloat16 h0, h1, h2, h3, l0, l1, l2, l3;
            bf_split(v.x, h0, l0); bf_split(v.y, h1, l1);
            bf_split(v.z, h2, l2); bf_split(v.w, h3, l3);
            int off = r * STR + c;
            *(uint2*)(Bh + off) = make_uint2(pack_bf(h0, h1), pack_bf(h2, h3));
            *(uint2*)(Bl + off) = make_uint2(pack_bf(l0, l1), pack_bf(l2, l3));
        }
        __syncthreads();

#pragma unroll
        for (int ks = 0; ks < 2; ++ks) {
            const int kb = ks * 16 + ksel;
            uint32_t bh[2][4], bl[2][4];
#pragma unroll
            for (int ntt = 0; ntt < 2; ++ntt) {
                uint32_t boff = ((warp_n + ntt * 16 + rsel) * STR + kb) * 2;
                ldm_x4(bh[ntt][0], bh[ntt][1], bh[ntt][2], bh[ntt][3], sBh + boff);
                ldm_x4(bl[ntt][0], bl[ntt][1], bl[ntt][2], bl[ntt][3], sBl + boff);
            }
#pragma unroll
            for (int mt = 0; mt < 4; ++mt) {
                uint32_t aoff = ((warp_m + mt * 16 + rsel) * STR + kb) * 2;
                uint32_t ah[4], al[4];
                ldm_x4(ah[0], ah[1], ah[2], ah[3], sAh + aoff);
                ldm_x4(al[0], al[1], al[2], al[3], sAl + aoff);
#pragma unroll
                for (int nt = 0; nt < 4; ++nt) {
                    uint32_t b0h = bh[nt >> 1][nt & 1];
                    uint32_t b1h = bh[nt >> 1][2 + (nt & 1)];
                    uint32_t b0l = bl[nt >> 1][nt & 1];
                    uint32_t b1l = bl[nt >> 1][2 + (nt & 1)];
                    mma_bf16(acc[mt][nt], ah, b0h, b1h);
                    mma_bf16(acc[mt][nt], ah, b0l, b1l);
                    mma_bf16(acc[mt][nt], al, b0h, b1h);
                }
            }
        }
        __syncthreads();
    }

    const int cr = lane >> 2;
    const int cc = (lane & 3) * 2;
#pragma unroll
    for (int mt = 0; mt < 4; ++mt) {
#pragma unroll
        for (int nt = 0; nt < 4; ++nt) {
            int jr = n0 + warp_n + nt * 8 + cc;
#pragma unroll
            for (int half = 0; half < 2; ++half) {
                int m = m0 + warp_m + mt * 16 + cr + half * 8;
                float e0 = acc[mt][nt][half * 2 + 0];
                float e1 = acc[mt][nt][half * 2 + 1];
                if (MODE == 0) {
                    int b = m >> 10, n = m & 1023;
                    int s = jr / CC;
                    int rr = jr - s * CC;
                    int h = rr >> 6, d = rr & 63;
                    float* dst = &g_qkv[((((size_t)s * BB + b) * HH + h) * NN + n) * HD + d];
                    *(float2*)dst = make_float2(e0, e1);
                } else {
                    float2 bv = *(const float2*)(bias + jr);
                    float* dst = &Cout[(size_t)m * CC + jr];
                    *(float2*)dst = make_float2(e0 + bv.x, e1 + bv.y);
                }
            }
        }
    }
}

// ===========================================================================
// Flash-style attention with mma.sync bf16 (3-term split) + online softmax.
// CTA: 128 q-rows x full head (d=64). 256 threads = 8 warps x 16 q-rows.
// KV processed in 8 tiles of 128 keys. V staged transposed for PV B-operand.
// ===========================================================================
#define QSTR 72     // bf16 stride for [row][d] tiles (144B, conflict-free ldmatrix)
#define VSTR 136    // bf16 stride for Vt [d][key] tiles (272B)
#define SA_QH 0
#define SA_QL 18432
#define SA_KH 36864
#define SA_KL 55296
#define SA_VH 73728
#define SA_VL 91136
#define SA_POL 108544
#define SA_TOT 112640
#define ASCALE 0.125f

__global__ __launch_bounds__(256, 1) void attn_mma(const float* __restrict__ policy)
{
    extern __shared__ __align__(16) char smb[];
    __nv_bfloat16* Qh = (__nv_bfloat16*)(smb + SA_QH);
    __nv_bfloat16* Ql = (__nv_bfloat16*)(smb + SA_QL);
    __nv_bfloat16* Kh = (__nv_bfloat16*)(smb + SA_KH);
    __nv_bfloat16* Kl = (__nv_bfloat16*)(smb + SA_KL);
    __nv_bfloat16* Vh = (__nv_bfloat16*)(smb + SA_VH);
    __nv_bfloat16* Vl = (__nv_bfloat16*)(smb + SA_VL);
    float*         POL = (float*)(smb + SA_POL);

    const int qt = blockIdx.x;     // 0..7 (128-row q tiles)
    const int bh = blockIdx.y;     // 0..191
    const int b  = bh / HH;
    const int h  = bh - b * HH;
    const int t    = threadIdx.x;
    const int wid  = t >> 5;
    const int lane = t & 31;
    const int rsel = lane & 15;
    const int ksel = (lane >> 4) * 8;
    const int m0 = qt * 128;

    const size_t plane = (size_t)NN * HD;
    const float* Qg = g_qkv + ((size_t)(0 * BB + b) * HH + h) * plane + (size_t)m0 * HD;
    const float* Kg = g_qkv + ((size_t)(1 * BB + b) * HH + h) * plane;
    const float* Vg = g_qkv + ((size_t)(2 * BB + b) * HH + h) * plane;

    // ---- load policy + Q tile (split) ----
    for (int j = t; j < NN; j += 256) POL[j] = policy[b * NN + j];
#pragma unroll
    for (int i = 0; i < 8; ++i) {
        int idx = t + 256 * i;                 // 2048 float4s = 128x64
        int r = idx >> 4, c = (idx & 15) * 4;
        float4 v = *(const float4*)(Qg + (size_t)r * HD + c);
        __nv_bfloat16 h0, h1, h2, h3, l0, l1, l2, l3;
        bf_split(v.x, h0, l0); bf_split(v.y, h1, l1);
        bf_split(v.z, h2, l2); bf_split(v.w, h3, l3);
        int off = r * QSTR + c;
        *(uint2*)(Qh + off) = make_uint2(pack_bf(h0, h1), pack_bf(h2, h3));
        *(uint2*)(Ql + off) = make_uint2(pack_bf(l0, l1), pack_bf(l2, l3));
    }
    __syncthreads();

    // ---- preload Q fragments (fixed all kernel) ----
    const uint32_t sQh = smem_u32(Qh), sQl = smem_u32(Ql);
    const uint32_t sKh = smem_u32(Kh), sKl = smem_u32(Kl);
    const uint32_t sVh = smem_u32(Vh), sVl = smem_u32(Vl);
    uint32_t qh[4][4], ql[4][4];
    {
        int qrow = wid * 16 + rsel;
#pragma unroll
        for (int ks = 0; ks < 4; ++ks) {
            uint32_t off = (uint32_t)(qrow * QSTR + ks * 16 + ksel) * 2;
            ldm_x4(qh[ks][0], qh[ks][1], qh[ks][2], qh[ks][3], sQh + off);
            ldm_x4(ql[ks][0], ql[ks][1], ql[ks][2], ql[ks][3], sQl + off);
        }
    }

    float o[8][4];
#pragma unroll
    for (int i = 0; i < 8; ++i)
#pragma unroll
        for (int j = 0; j < 4; ++j) o[i][j] = 0.f;
    float l0 = 0.f, l1 = 0.f;
    float mm0 = -1e30f, mm1 = -1e30f;
    const int g0 = m0 + wid * 16 + (lane >> 2);   // global q row (first half)
    const int g1 = g0 + 8;

    for (int kv = 0; kv < 8; ++kv) {
        __syncthreads();   // previous tile fully consumed

        // ---- stage K tile (split) and V tile (split, transposed) ----
#pragma unroll
        for (int i = 0; i < 8; ++i) {
            int idx = t + 256 * i;
            int key = idx >> 4, c = (idx & 15) * 4;
            float4 v = *(const float4*)(Kg + (size_t)(kv * 128 + key) * HD + c);
            __nv_bfloat16 h0, h1, h2, h3, q0, q1, q2, q3;
            bf_split(v.x, h0, q0); bf_split(v.y, h1, q1);
            bf_split(v.z, h2, q2); bf_split(v.w, h3, q3);
            int off = key * QSTR + c;
            *(uint2*)(Kh + off) = make_uint2(pack_bf(h0, h1), pack_bf(h2, h3));
            *(uint2*)(Kl + off) = make_uint2(pack_bf(q0, q1), pack_bf(q2, q3));
        }
#pragma unroll
        for (int i = 0; i < 8; ++i) {
            int idx = t + 256 * i;
            int key = idx >> 4, c = (idx & 15) * 4;
            float4 v = *(const float4*)(Vg + (size_t)(kv * 128 + key) * HD + c);
            const float* ve = &v.x;
#pragma unroll
            for (int e = 0; e < 4; ++e) {
                __nv_bfloat16 hh, ll;
                bf_split(ve[e], hh, ll);
                Vh[(c + e) * VSTR + key] = hh;
                Vl[(c + e) * VSTR + key] = ll;
            }
        }
        __syncthreads();

        // ---- S = Q @ K^T (16 q-rows x 128 keys per warp) ----
        float s[16][4];
#pragma unroll
        for (int i = 0; i < 16; ++i)
#pragma unroll
            for (int j = 0; j < 4; ++j) s[i][j] = 0.f;

#pragma unroll
        for (int kb = 0; kb < 8; ++kb) {
#pragma unroll
            for (int ks = 0; ks < 4; ++ks) {
                uint32_t off = (uint32_t)((kb * 16 + rsel) * QSTR + ks * 16 + ksel) * 2;
                uint32_t kh[4], kl[4];
                ldm_x4(kh[0], kh[1], kh[2], kh[3], sKh + off);
                ldm_x4(kl[0], kl[1], kl[2], kl[3], sKl + off);
                mma_bf16(s[2 * kb + 0], qh[ks], kh[0], kh[2]);
                mma_bf16(s[2 * kb + 0], qh[ks], kl[0], kl[2]);
                mma_bf16(s[2 * kb + 0], ql[ks], kh[0], kh[2]);
                mma_bf16(s[2 * kb + 1], qh[ks], kh[1], kh[3]);
                mma_bf16(s[2 * kb + 1], qh[ks], kl[1], kl[3]);
                mma_bf16(s[2 * kb + 1], ql[ks], kh[1], kh[3]);
            }
        }

        // ---- online softmax update ----
        float mx0 = -1e30f, mx1 = -1e30f;
#pragma unroll
        for (int nt = 0; nt < 16; ++nt) {
            mx0 = fmaxf(mx0, fmaxf(s[nt][0], s[nt][1]));
            mx1 = fmaxf(mx1, fmaxf(s[nt][2], s[nt][3]));
        }
        mx0 = fmaxf(mx0, __shfl_xor_sync(0xffffffffu, mx0, 1));
        mx0 = fmaxf(mx0, __shfl_xor_sync(0xffffffffu, mx0, 2));
        mx1 = fmaxf(mx1, __shfl_xor_sync(0xffffffffu, mx1, 1));
        mx1 = fmaxf(mx1, __shfl_xor_sync(0xffffffffu, mx1, 2));

        float nm0 = fmaxf(mm0, mx0);
        float nm1 = fmaxf(mm1, mx1);
        float al0 = __expf((mm0 - nm0) * ASCALE);
        float al1 = __expf((mm1 - nm1) * ASCALE);
        mm0 = nm0; mm1 = nm1;
        l0 *= al0; l1 *= al1;
#pragma unroll
        for (int nt = 0; nt < 8; ++nt) {
            o[nt][0] *= al0; o[nt][1] *= al0;
            o[nt][2] *= al1; o[nt][3] *= al1;
        }

        const int jb0 = kv * 128 + 2 * (lane & 3);
        float sum0 = 0.f, sum1 = 0.f;
#pragma unroll
        for (int nt = 0; nt < 16; ++nt) {
            int j0 = jb0 + nt * 8;
            float w0 = (j0 == g0) ? 1.f : POL[j0];
            float w1 = (j0 + 1 == g0) ? 1.f : POL[j0 + 1];
            float w2 = (j0 == g1) ? 1.f : POL[j0];
            float w3 = (j0 + 1 == g1) ? 1.f : POL[j0 + 1];
            float p0 = __expf((s[nt][0] - nm0) * ASCALE) * w0;
            float p1 = __expf((s[nt][1] - nm0) * ASCALE) * w1;
            float p2 = __expf((s[nt][2] - nm1) * ASCALE) * w2;
            float p3 = __expf((s[nt][3] - nm1) * ASCALE) * w3;
            sum0 += p0 + p1; sum1 += p2 + p3;
            s[nt][0] = p0; s[nt][1] = p1; s[nt][2] = p2; s[nt][3] = p3;
        }
        sum0 += __shfl_xor_sync(0xffffffffu, sum0, 1);
        sum0 += __shfl_xor_sync(0xffffffffu, sum0, 2);
        sum1 += __shfl_xor_sync(0xffffffffu, sum1, 1);
        sum1 += __shfl_xor_sync(0xffffffffu, sum1, 2);
        l0 += sum0; l1 += sum1;

        // ---- O += P @ V (P split to bf16 hi/lo from S accumulators) ----
#pragma unroll
        for (int kb = 0; kb < 8; ++kb) {
            __nv_bfloat16 hA, lA, hB, lB;
            uint32_t pah[4], pal[4];
            bf_split(s[2 * kb][0], hA, lA); bf_split(s[2 * kb][1], hB, lB);
            pah[0] = pack_bf(hA, hB); pal[0] = pack_bf(lA, lB);
            bf_split(s[2 * kb][2], hA, lA); bf_split(s[2 * kb][3], hB, lB);
            pah[1] = pack_bf(hA, hB); pal[1] = pack_bf(lA, lB);
            bf_split(s[2 * kb + 1][0], hA, lA); bf_split(s[2 * kb + 1][1], hB, lB);
            pah[2] = pack_bf(hA, hB); pal[2] = pack_bf(lA, lB);
            bf_split(s[2 * kb + 1][2], hA, lA); bf_split(s[2 * kb + 1][3], hB, lB);
            pah[3] = pack_bf(hA, hB); pal[3] = pack_bf(lA, lB);

#pragma unroll
            for (int np = 0; np < 4; ++np) {
                uint32_t off = (uint32_t)((np * 16 + rsel) * VSTR + kb * 16 + ksel) * 2;
                uint32_t vh[4], vl[4];
                ldm_x4(vh[0], vh[1], vh[2], vh[3], sVh + off);
                ldm_x4(vl[0], vl[1], vl[2], vl[3], sVl + off);
                mma_bf16(o[2 * np + 0], pah, vh[0], vh[2]);
                mma_bf16(o[2 * np + 0], pah, vl[0], vl[2]);
                mma_bf16(o[2 * np + 0], pal, vh[0], vh[2]);
                mma_bf16(o[2 * np + 1], pah, vh[1], vh[3]);
                mma_bf16(o[2 * np + 1], pah, vl[1], vl[3]);
                mma_bf16(o[2 * np + 1], pal, vh[1], vh[3]);
            }
        }
    }

    // ---- epilogue: normalize and write to g_att [B][N][C] ----
    const float inv0 = 1.0f / (l0 + 1e-6f);
    const float inv1 = 1.0f / (l1 + 1e-6f);
    const int d0 = (lane & 3) * 2;
#pragma unroll
    for (int nt = 0; nt < 8; ++nt) {
        int d = nt * 8 + d0;
        float* dst0 = g_att + ((size_t)b * NN + g0) * CC + h * HD + d;
        float* dst1 = g_att + ((size_t)b * NN + g1) * CC + h * HD + d;
        *(float2*)dst0 = make_float2(o[nt][0] * inv0, o[nt][1] * inv0);
        *(float2*)dst1 = make_float2(o[nt][2] * inv1, o[nt][3] * inv1);
    }
}

// ===========================================================================
// Launch
// ===========================================================================
extern "C" void kernel_launch(void* const* d_in, const int* in_sizes, int n_in,
                              void* d_out, int out_size)
{
    const float* x      = (const float*)d_in[0];   // [16, 1024, 768]
    const float* policy = (const float*)d_in[1];   // [16, 1024, 1]
    const float* w_qkv  = (const float*)d_in[2];   // [2304, 768]
    const float* w_proj = (const float*)d_in[3];   // [768, 768]
    const float* b_proj = (const float*)d_in[4];   // [768]
    float* out = (float*)d_out;                    // [16, 1024, 768]

    (void)in_sizes; (void)n_in; (void)out_size;

    cudaFuncSetAttribute(attn_mma, cudaFuncAttributeMaxDynamicSharedMemorySize, SA_TOT);

    // QKV GEMM
    {
        dim3 grid(2304 / BN, 16384 / BM);
        tc_gemm<0><<<grid, 256>>>(x, w_qkv, nullptr, nullptr, CC);
    }
    // Attention (flash-style, mma.sync)
    {
        dim3 grid(8, BB * HH);
        attn_mma<<<grid, 256, SA_TOT>>>(policy);
    }
    // Projection
    {
        dim3 grid(CC / BN, 16384 / BM);
        tc_gemm<1><<<grid, 256>>>(nullptr, w_proj, b_proj, out, CC);
    }
}

// round 8
// speedup vs baseline: 4.3144x; 1.3802x over previous
#include <cuda_runtime.h>
#include <cuda_bf16.h>
#include <cstdint>
#include <math.h>

// Problem constants
#define BB 16
#define NN 1024
#define CC 768
#define HH 12
#define HD 64

// ---------------------------------------------------------------------------
// Device-global scratch: split bf16 planes (hi + lo residual)
// ---------------------------------------------------------------------------
__device__ __nv_bfloat16 g_xs_h[(size_t)BB * NN * CC];
__device__ __nv_bfloat16 g_xs_l[(size_t)BB * NN * CC];
__device__ __nv_bfloat16 g_wq_h[(size_t)3 * CC * CC];
__device__ __nv_bfloat16 g_wq_l[(size_t)3 * CC * CC];
__device__ __nv_bfloat16 g_wp_h[(size_t)CC * CC];
__device__ __nv_bfloat16 g_wp_l[(size_t)CC * CC];
__device__ __nv_bfloat16 g_qkv_h[(size_t)3 * BB * HH * NN * HD];  // [3][B][H][N][HD]
__device__ __nv_bfloat16 g_qkv_l[(size_t)3 * BB * HH * NN * HD];
__device__ __nv_bfloat16 g_att_h[(size_t)BB * NN * CC];           // [B][N][C]
__device__ __nv_bfloat16 g_att_l[(size_t)BB * NN * CC];

// ===========================================================================
// Helpers (plain sm_80+ PTX)
// ===========================================================================
__device__ __forceinline__ uint32_t smem_u32(const void* p) {
    uint32_t a;
    asm("{ .reg .u64 t; cvta.to.shared.u64 t, %1; cvt.u32.u64 %0, t; }"
        : "=r"(a) : "l"(p));
    return a;
}
__device__ __forceinline__ void ldm_x4(uint32_t& r0, uint32_t& r1,
                                       uint32_t& r2, uint32_t& r3, uint32_t addr) {
    asm volatile("ldmatrix.sync.aligned.m8n8.x4.shared.b16 {%0,%1,%2,%3}, [%4];"
                 : "=r"(r0), "=r"(r1), "=r"(r2), "=r"(r3) : "r"(addr));
}
__device__ __forceinline__ void ldm_x4_t(uint32_t& r0, uint32_t& r1,
                                         uint32_t& r2, uint32_t& r3, uint32_t addr) {
    asm volatile("ldmatrix.sync.aligned.m8n8.x4.trans.shared.b16 {%0,%1,%2,%3}, [%4];"
                 : "=r"(r0), "=r"(r1), "=r"(r2), "=r"(r3) : "r"(addr));
}
__device__ __forceinline__ void mma_bf16(float* c, const uint32_t* a,
                                         uint32_t b0, uint32_t b1) {
    asm volatile(
        "mma.sync.aligned.m16n8k16.row.col.f32.bf16.bf16.f32 "
        "{%0,%1,%2,%3}, {%4,%5,%6,%7}, {%8,%9}, {%0,%1,%2,%3};"
        : "+f"(c[0]), "+f"(c[1]), "+f"(c[2]), "+f"(c[3])
        : "r"(a[0]), "r"(a[1]), "r"(a[2]), "r"(a[3]), "r"(b0), "r"(b1));
}
__device__ __forceinline__ uint32_t pack_bf(__nv_bfloat16 a, __nv_bfloat16 b) {
    uint32_t ua = (uint32_t)__bfloat16_as_ushort(a);
    uint32_t ub = (uint32_t)__bfloat16_as_ushort(b);
    return ua | (ub << 16);
}
__device__ __forceinline__ void bf_split(float x, __nv_bfloat16& h, __nv_bfloat16& l) {
    h = __float2bfloat16(x);
    l = __float2bfloat16(x - __bfloat162float(h));
}
__device__ __forceinline__ void cp_async16(uint32_t dst, const void* src) {
    asm volatile("cp.async.cg.shared.global [%0], [%1], 16;" :: "r"(dst), "l"(src));
}
#define CP_COMMIT() asm volatile("cp.async.commit_group;" ::: "memory")
#define CP_WAIT1()  asm volatile("cp.async.wait_group 1;" ::: "memory")

// ===========================================================================
// Split kernel: fp32 -> (hi, lo) bf16 planes, vectorized float4 -> uint2
// ===========================================================================
__global__ void split_kernel(const float* __restrict__ src,
                             __nv_bfloat16* __restrict__ hi,
                             __nv_bfloat16* __restrict__ lo, int n4)
{
    int i = blockIdx.x * blockDim.x + threadIdx.x;
    if (i >= n4) return;
    float4 v = ((const float4*)src)[i];
    __nv_bfloat16 h0, h1, h2, h3, l0, l1, l2, l3;
    bf_split(v.x, h0, l0); bf_split(v.y, h1, l1);
    bf_split(v.z, h2, l2); bf_split(v.w, h3, l3);
    ((uint2*)hi)[i] = make_uint2(pack_bf(h0, h1), pack_bf(h2, h3));
    ((uint2*)lo)[i] = make_uint2(pack_bf(l0, l1), pack_bf(l2, l3));
}

// ===========================================================================
// Double-buffered bf16 mma.sync GEMM (3-term split), conversion-free mainloop.
// C[M,Ncols] = A[M,K] @ W[Ncols,K]^T.  Tile 128x128, BK=32, 256 threads.
// MODE 0: epilogue splits + scatters into g_qkv_h/l planes.
// MODE 1: epilogue adds bias, writes fp32 Cout.
// ===========================================================================
#define BM 128
#define BN 128
#define BK 32
#define STR 40
#define TILE_B (BM * STR * 2)            // 10240 bytes per tile
#define OFF_AH 0
#define OFF_AL (TILE_B)
#define OFF_BH (2 * TILE_B)
#define OFF_BL (3 * TILE_B)
#define STAGE_B (4 * TILE_B)             // 40960
#define SM_GEMM (2 * STAGE_B)            // 81920

template <int MODE>
__global__ __launch_bounds__(256) void tc_gemm(
    const __nv_bfloat16* __restrict__ Ah_g, const __nv_bfloat16* __restrict__ Al_g,
    const __nv_bfloat16* __restrict__ Wh_g, const __nv_bfloat16* __restrict__ Wl_g,
    const float* __restrict__ bias, float* __restrict__ Cout, int K)
{
    extern __shared__ __align__(128) char dsm[];
    const uint32_t sb = smem_u32(dsm);

    const int t    = threadIdx.x;
    const int wid  = t >> 5;
    const int lane = t & 31;
    const int m0   = blockIdx.y * BM;
    const int n0   = blockIdx.x * BN;

    const int warp_m = (wid & 1) * 64;
    const int warp_n = (wid >> 1) * 32;
    const int rsel = lane & 15;
    const int ksel = (lane >> 4) * 8;

    // cp.async load coords: 512 chunks of 16B per tile, 2 per thread
    const int lr0 = (t * 2) >> 2;            // row of chunk pair base
    // chunk idx = 2t, 2t+1 -> rows (2t)/4, cols ((2t)&3)
    auto load_stage = [&](int ck, int st) {
        const int k0 = ck * BK;
        const uint32_t base = sb + st * STAGE_B;
#pragma unroll
        for (int i = 0; i < 2; ++i) {
            int idx = 2 * t + i;
            int r = idx >> 2, c = idx & 3;             // c*8 bf16 elems
            uint32_t doff = (uint32_t)(r * STR + c * 8) * 2;
            const __nv_bfloat16* a_h = Ah_g + (size_t)(m0 + r) * K + k0 + c * 8;
            const __nv_bfloat16* a_l = Al_g + (size_t)(m0 + r) * K + k0 + c * 8;
            const __nv_bfloat16* b_h = Wh_g + (size_t)(n0 + r) * K + k0 + c * 8;
            const __nv_bfloat16* b_l = Wl_g + (size_t)(n0 + r) * K + k0 + c * 8;
            cp_async16(base + OFF_AH + doff, a_h);
            cp_async16(base + OFF_AL + doff, a_l);
            cp_async16(base + OFF_BH + doff, b_h);
            cp_async16(base + OFF_BL + doff, b_l);
        }
    };

    float acc[4][4][4];
#pragma unroll
    for (int i = 0; i < 4; ++i)
#pragma unroll
        for (int j = 0; j < 4; ++j)
#pragma unroll
            for (int k = 0; k < 4; ++k) acc[i][j][k] = 0.f;

    const int nchunks = K / BK;   // 24
    load_stage(0, 0);
    CP_COMMIT();

    for (int ck = 0; ck < nchunks; ++ck) {
        if (ck + 1 < nchunks) load_stage(ck + 1, (ck + 1) & 1);
        CP_COMMIT();
        CP_WAIT1();
        __syncthreads();

        const uint32_t stb = sb + (ck & 1) * STAGE_B;
        const uint32_t sAh = stb + OFF_AH, sAl = stb + OFF_AL;
        const uint32_t sBh = stb + OFF_BH, sBl = stb + OFF_BL;

#pragma unroll
        for (int ks = 0; ks < 2; ++ks) {
            const int kb = ks * 16 + ksel;
            uint32_t bh[2][4], bl[2][4];
#pragma unroll
            for (int ntt = 0; ntt < 2; ++ntt) {
                uint32_t boff = (uint32_t)((warp_n + ntt * 16 + rsel) * STR + kb) * 2;
                ldm_x4(bh[ntt][0], bh[ntt][1], bh[ntt][2], bh[ntt][3], sBh + boff);
                ldm_x4(bl[ntt][0], bl[ntt][1], bl[ntt][2], bl[ntt][3], sBl + boff);
            }
#pragma unroll
            for (int mt = 0; mt < 4; ++mt) {
                uint32_t aoff = (uint32_t)((warp_m + mt * 16 + rsel) * STR + kb) * 2;
                uint32_t ah[4], al[4];
                ldm_x4(ah[0], ah[1], ah[2], ah[3], sAh + aoff);
                ldm_x4(al[0], al[1], al[2], al[3], sAl + aoff);
#pragma unroll
                for (int nt = 0; nt < 4; ++nt) {
                    uint32_t b0h = bh[nt >> 1][nt & 1];
                    uint32_t b1h = bh[nt >> 1][2 + (nt & 1)];
                    uint32_t b0l = bl[nt >> 1][nt & 1];
                    uint32_t b1l = bl[nt >> 1][2 + (nt & 1)];
                    mma_bf16(acc[mt][nt], ah, b0h, b1h);
                    mma_bf16(acc[mt][nt], ah, b0l, b1l);
                    mma_bf16(acc[mt][nt], al, b0h, b1h);
                }
            }
        }
        __syncthreads();
    }

    const int cr = lane >> 2;
    const int cc = (lane & 3) * 2;
#pragma unroll
    for (int mt = 0; mt < 4; ++mt) {
#pragma unroll
        for (int nt = 0; nt < 4; ++nt) {
            int jr = n0 + warp_n + nt * 8 + cc;
#pragma unroll
            for (int half = 0; half < 2; ++half) {
                int m = m0 + warp_m + mt * 16 + cr + half * 8;
                float e0 = acc[mt][nt][half * 2 + 0];
                float e1 = acc[mt][nt][half * 2 + 1];
                if (MODE == 0) {
                    int b = m >> 10, n = m & 1023;
                    int s = jr / CC;
                    int rr = jr - s * CC;
                    int h = rr >> 6, d = rr & 63;
                    size_t idx = ((((size_t)s * BB + b) * HH + h) * NN + n) * HD + d;
                    __nv_bfloat16 h0, h1, l0, l1;
                    bf_split(e0, h0, l0); bf_split(e1, h1, l1);
                    *(uint32_t*)&g_qkv_h[idx] = pack_bf(h0, h1);
                    *(uint32_t*)&g_qkv_l[idx] = pack_bf(l0, l1);
                } else {
                    float2 bv = *(const float2*)(bias + jr);
                    float* dst = &Cout[(size_t)m * CC + jr];
                    *(float2*)dst = make_float2(e0 + bv.x, e1 + bv.y);
                }
            }
        }
    }
}

// ===========================================================================
// Flash attention, mma.sync bf16 3-term split, conversion-free staging.
// CTA: 128 q-rows x head. 8 warps x 16 q-rows. KV in 8 tiles of 128 keys.
// V staged row-major [key][d]; PV B-fragments via ldmatrix.trans.
// ===========================================================================
#define QSTR 72
#define ATILE (128 * QSTR * 2)        // 18432 B per tile
#define SA_QH 0
#define SA_QL (1 * ATILE)
#define SA_KH (2 * ATILE)
#define SA_KL (3 * ATILE)
#define SA_VH (4 * ATILE)
#define SA_VL (5 * ATILE)
#define SA_POL (6 * ATILE)
#define SA_TOT (6 * ATILE + 4096)     // 114688
#define ASCALE 0.125f

__global__ __launch_bounds__(256, 1) void attn_mma(const float* __restrict__ policy)
{
    extern __shared__ __align__(16) char smb[];
    __nv_bfloat16* Qh = (__nv_bfloat16*)(smb + SA_QH);
    __nv_bfloat16* Ql = (__nv_bfloat16*)(smb + SA_QL);
    __nv_bfloat16* Kh = (__nv_bfloat16*)(smb + SA_KH);
    __nv_bfloat16* Kl = (__nv_bfloat16*)(smb + SA_KL);
    __nv_bfloat16* Vh = (__nv_bfloat16*)(smb + SA_VH);
    __nv_bfloat16* Vl = (__nv_bfloat16*)(smb + SA_VL);
    float*        POL = (float*)(smb + SA_POL);

    const int qt = blockIdx.x;
    const int bh = blockIdx.y;
    const int b  = bh / HH;
    const int h  = bh - b * HH;
    const int t    = threadIdx.x;
    const int wid  = t >> 5;
    const int lane = t & 31;
    const int rsel = lane & 15;
    const int ksel = (lane >> 4) * 8;
    const int m0 = qt * 128;

    const size_t plane = (size_t)NN * HD;
    const size_t hoff  = ((size_t)b * HH + h) * plane;
    const __nv_bfloat16* Qg_h = g_qkv_h + hoff + (size_t)m0 * HD;
    const __nv_bfloat16* Qg_l = g_qkv_l + hoff + (size_t)m0 * HD;
    const __nv_bfloat16* Kg_h = g_qkv_h + (size_t)BB * HH * plane + hoff;
    const __nv_bfloat16* Kg_l = g_qkv_l + (size_t)BB * HH * plane + hoff;
    const __nv_bfloat16* Vg_h = g_qkv_h + 2 * (size_t)BB * HH * plane + hoff;
    const __nv_bfloat16* Vg_l = g_qkv_l + 2 * (size_t)BB * HH * plane + hoff;

    // ---- stage policy + Q ----
    for (int j = t; j < NN; j += 256) POL[j] = policy[b * NN + j];
#pragma unroll
    for (int i = 0; i < 4; ++i) {
        int idx = t + 256 * i;              // 1024 chunks of 8 bf16
        int r = idx >> 3, c8 = (idx & 7) * 8;
        *(uint4*)(Qh + r * QSTR + c8) = *(const uint4*)(Qg_h + (size_t)r * HD + c8);
        *(uint4*)(Ql + r * QSTR + c8) = *(const uint4*)(Qg_l + (size_t)r * HD + c8);
    }
    __syncthreads();

    const uint32_t sQh = smem_u32(Qh), sQl = smem_u32(Ql);
    const uint32_t sKh = smem_u32(Kh), sKl = smem_u32(Kl);
    const uint32_t sVh = smem_u32(Vh), sVl = smem_u32(Vl);

    uint32_t qh[4][4], ql[4][4];
    {
        int qrow = wid * 16 + rsel;
#pragma unroll
        for (int ks = 0; ks < 4; ++ks) {
            uint32_t off = (uint32_t)(qrow * QSTR + ks * 16 + ksel) * 2;
            ldm_x4(qh[ks][0], qh[ks][1], qh[ks][2], qh[ks][3], sQh + off);
            ldm_x4(ql[ks][0], ql[ks][1], ql[ks][2], ql[ks][3], sQl + off);
        }
    }

    float o[8][4];
#pragma unroll
    for (int i = 0; i < 8; ++i)
#pragma unroll
        for (int j = 0; j < 4; ++j) o[i][j] = 0.f;
    float l0 = 0.f, l1 = 0.f;
    float mm0 = -1e30f, mm1 = -1e30f;
    const int g0 = m0 + wid * 16 + (lane >> 2);
    const int g1 = g0 + 8;

    // PV trans-ldmatrix address components (per lane)
    const int v_key8 = ((lane >> 3) & 1) * 8 + (lane & 7);   // key offset in 16-block
    const int v_d8   = (lane >> 4) * 8;                      // d offset in 16-block

    for (int kv = 0; kv < 8; ++kv) {
        __syncthreads();

        // ---- stage K and V tiles (plain bf16 copies) ----
#pragma unroll
        for (int i = 0; i < 4; ++i) {
            int idx = t + 256 * i;
            int r = idx >> 3, c8 = (idx & 7) * 8;
            size_t gsrc = (size_t)(kv * 128 + r) * HD + c8;
            int doff = r * QSTR + c8;
            *(uint4*)(Kh + doff) = *(const uint4*)(Kg_h + gsrc);
            *(uint4*)(Kl + doff) = *(const uint4*)(Kg_l + gsrc);
            *(uint4*)(Vh + doff) = *(const uint4*)(Vg_h + gsrc);
            *(uint4*)(Vl + doff) = *(const uint4*)(Vg_l + gsrc);
        }
        __syncthreads();

        // ---- S = Q @ K^T ----
        float s[16][4];
#pragma unroll
        for (int i = 0; i < 16; ++i)
#pragma unroll
            for (int j = 0; j < 4; ++j) s[i][j] = 0.f;

#pragma unroll
        for (int kb = 0; kb < 8; ++kb) {
#pragma unroll
            for (int ks = 0; ks < 4; ++ks) {
                uint32_t off = (uint32_t)((kb * 16 + rsel) * QSTR + ks * 16 + ksel) * 2;
                uint32_t kh[4], kl[4];
                ldm_x4(kh[0], kh[1], kh[2], kh[3], sKh + off);
                ldm_x4(kl[0], kl[1], kl[2], kl[3], sKl + off);
                mma_bf16(s[2 * kb + 0], qh[ks], kh[0], kh[2]);
                mma_bf16(s[2 * kb + 0], qh[ks], kl[0], kl[2]);
                mma_bf16(s[2 * kb + 0], ql[ks], kh[0], kh[2]);
                mma_bf16(s[2 * kb + 1], qh[ks], kh[1], kh[3]);
                mma_bf16(s[2 * kb + 1], qh[ks], kl[1], kl[3]);
                mma_bf16(s[2 * kb + 1], ql[ks], kh[1], kh[3]);
            }
        }

        // ---- online softmax ----
        float mx0 = -1e30f, mx1 = -1e30f;
#pragma unroll
        for (int nt = 0; nt < 16; ++nt) {
            mx0 = fmaxf(mx0, fmaxf(s[nt][0], s[nt][1]));
            mx1 = fmaxf(mx1, fmaxf(s[nt][2], s[nt][3]));
        }
        mx0 = fmaxf(mx0, __shfl_xor_sync(0xffffffffu, mx0, 1));
        mx0 = fmaxf(mx0, __shfl_xor_sync(0xffffffffu, mx0, 2));
        mx1 = fmaxf(mx1, __shfl_xor_sync(0xffffffffu, mx1, 1));
        mx1 = fmaxf(mx1, __shfl_xor_sync(0xffffffffu, mx1, 2));

        float nm0 = fmaxf(mm0, mx0);
        float nm1 = fmaxf(mm1, mx1);
        float al0 = __expf((mm0 - nm0) * ASCALE);
        float al1 = __expf((mm1 - nm1) * ASCALE);
        mm0 = nm0; mm1 = nm1;
        l0 *= al0; l1 *= al1;
#pragma unroll
        for (int nt = 0; nt < 8; ++nt) {
            o[nt][0] *= al0; o[nt][1] *= al0;
            o[nt][2] *= al1; o[nt][3] *= al1;
        }

        const int jb0 = kv * 128 + 2 * (lane & 3);
        float sum0 = 0.f, sum1 = 0.f;
#pragma unroll
        for (int nt = 0; nt < 16; ++nt) {
            int j0 = jb0 + nt * 8;
            float w0 = (j0 == g0) ? 1.f : POL[j0];
            float w1 = (j0 + 1 == g0) ? 1.f : POL[j0 + 1];
            float w2 = (j0 == g1) ? 1.f : POL[j0];
            float w3 = (j0 + 1 == g1) ? 1.f : POL[j0 + 1];
            float p0 = __expf((s[nt][0] - nm0) * ASCALE) * w0;
            float p1 = __expf((s[nt][1] - nm0) * ASCALE) * w1;
            float p2 = __expf((s[nt][2] - nm1) * ASCALE) * w2;
            float p3 = __expf((s[nt][3] - nm1) * ASCALE) * w3;
            sum0 += p0 + p1; sum1 += p2 + p3;
            s[nt][0] = p0; s[nt][1] = p1; s[nt][2] = p2; s[nt][3] = p3;
        }
        sum0 += __shfl_xor_sync(0xffffffffu, sum0, 1);
        sum0 += __shfl_xor_sync(0xffffffffu, sum0, 2);
        sum1 += __shfl_xor_sync(0xffffffffu, sum1, 1);
        sum1 += __shfl_xor_sync(0xffffffffu, sum1, 2);
        l0 += sum0; l1 += sum1;

        // ---- O += P @ V  (B-fragments via ldmatrix.trans on [key][d]) ----
#pragma unroll
        for (int kb = 0; kb < 8; ++kb) {
            __nv_bfloat16 hA, lA, hB, lB;
            uint32_t pah[4], pal[4];
            bf_split(s[2 * kb][0], hA, lA); bf_split(s[2 * kb][1], hB, lB);
            pah[0] = pack_bf(hA, hB); pal[0] = pack_bf(lA, lB);
            bf_split(s[2 * kb][2], hA, lA); bf_split(s[2 * kb][3], hB, lB);
            pah[1] = pack_bf(hA, hB); pal[1] = pack_bf(lA, lB);
            bf_split(s[2 * kb + 1][0], hA, lA); bf_split(s[2 * kb + 1][1], hB, lB);
            pah[2] = pack_bf(hA, hB); pal[2] = pack_bf(lA, lB);
            bf_split(s[2 * kb + 1][2], hA, lA); bf_split(s[2 * kb + 1][3], hB, lB);
            pah[3] = pack_bf(hA, hB); pal[3] = pack_bf(lA, lB);

            const int keyb = kb * 16 + v_key8;
#pragma unroll
            for (int dq = 0; dq < 4; ++dq) {
                uint32_t off = (uint32_t)(keyb * QSTR + dq * 16 + v_d8) * 2;
                uint32_t vh[4], vl[4];
                ldm_x4_t(vh[0], vh[1], vh[2], vh[3], sVh + off);
                ldm_x4_t(vl[0], vl[1], vl[2], vl[3], sVl + off);
                mma_bf16(o[2 * dq + 0], pah, vh[0], vh[1]);
                mma_bf16(o[2 * dq + 0], pah, vl[0], vl[1]);
                mma_bf16(o[2 * dq + 0], pal, vh[0], vh[1]);
                mma_bf16(o[2 * dq + 1], pah, vh[2], vh[3]);
                mma_bf16(o[2 * dq + 1], pah, vl[2], vl[3]);
                mma_bf16(o[2 * dq + 1], pal, vh[2], vh[3]);
            }
        }
    }

    // ---- epilogue: normalize, split, write g_att planes ----
    const float inv0 = 1.0f / (l0 + 1e-6f);
    const float inv1 = 1.0f / (l1 + 1e-6f);
    const int d0 = (lane & 3) * 2;
#pragma unroll
    for (int nt = 0; nt < 8; ++nt) {
        int d = nt * 8 + d0;
        size_t i0 = ((size_t)b * NN + g0) * CC + h * HD + d;
        size_t i1 = ((size_t)b * NN + g1) * CC + h * HD + d;
        __nv_bfloat16 h0, h1, lo0, lo1;
        bf_split(o[nt][0] * inv0, h0, lo0); bf_split(o[nt][1] * inv0, h1, lo1);
        *(uint32_t*)&g_att_h[i0] = pack_bf(h0, h1);
        *(uint32_t*)&g_att_l[i0] = pack_bf(lo0, lo1);
        bf_split(o[nt][2] * inv1, h0, lo0); bf_split(o[nt][3] * inv1, h1, lo1);
        *(uint32_t*)&g_att_h[i1] = pack_bf(h0, h1);
        *(uint32_t*)&g_att_l[i1] = pack_bf(lo0, lo1);
    }
}

// ===========================================================================
// Launch
// ===========================================================================
extern "C" void kernel_launch(void* const* d_in, const int* in_sizes, int n_in,
                              void* d_out, int out_size)
{
    const float* x      = (const float*)d_in[0];   // [16, 1024, 768]
    const float* policy = (const float*)d_in[1];   // [16, 1024, 1]
    const float* w_qkv  = (const float*)d_in[2];   // [2304, 768]
    const float* w_proj = (const float*)d_in[3];   // [768, 768]
    const float* b_proj = (const float*)d_in[4];   // [768]
    float* out = (float*)d_out;                    // [16, 1024, 768]

    (void)in_sizes; (void)n_in; (void)out_size;

    cudaFuncSetAttribute(tc_gemm<0>, cudaFuncAttributeMaxDynamicSharedMemorySize, SM_GEMM);
    cudaFuncSetAttribute(tc_gemm<1>, cudaFuncAttributeMaxDynamicSharedMemorySize, SM_GEMM);
    cudaFuncSetAttribute(attn_mma, cudaFuncAttributeMaxDynamicSharedMemorySize, SA_TOT);

    // resolve device-global plane addresses (host side)
    __nv_bfloat16 *xs_h, *xs_l, *wq_h, *wq_l, *wp_h, *wp_l;
    cudaGetSymbolAddress((void**)&xs_h, g_xs_h);
    cudaGetSymbolAddress((void**)&xs_l, g_xs_l);
    cudaGetSymbolAddress((void**)&wq_h, g_wq_h);
    cudaGetSymbolAddress((void**)&wq_l, g_wq_l);
    cudaGetSymbolAddress((void**)&wp_h, g_wp_h);
    cudaGetSymbolAddress((void**)&wp_l, g_wp_l);

    // 1) pre-split inputs to bf16 hi/lo planes
    {
        int n4x = BB * NN * CC / 4;            // 3,145,728
        split_kernel<<<(n4x + 255) / 256, 256>>>(x, xs_h, xs_l, n4x);
        int n4q = 3 * CC * CC / 4;             // 442,368
        split_kernel<<<(n4q + 255) / 256, 256>>>(w_qkv, wq_h, wq_l, n4q);
        int n4p = CC * CC / 4;                 // 147,456
        split_kernel<<<(n4p + 255) / 256, 256>>>(w_proj, wp_h, wp_l, n4p);
    }
    // 2) QKV GEMM -> split g_qkv planes
    {
        dim3 grid(2304 / BN, 16384 / BM);      // (18, 128)
        tc_gemm<0><<<grid, 256, SM_GEMM>>>(xs_h, xs_l, wq_h, wq_l, nullptr, nullptr, CC);
    }
    // 3) Flash attention -> split g_att planes
    {
        dim3 grid(8, BB * HH);
        attn_mma<<<grid, 256, SA_TOT>>>(policy);
    }
    // 4) Projection -> out (fp32 + bias)
    {
        __nv_bfloat16 *at_h, *at_l;
        cudaGetSymbolAddress((void**)&at_h, g_att_h);
        cudaGetSymbolAddress((void**)&at_l, g_att_l);
        dim3 grid(CC / BN, 16384 / BM);        // (6, 128)
        tc_gemm<1><<<grid, 256, SM_GEMM>>>(at_h, at_l, wp_h, wp_l, b_proj, out, CC);
    }
}

// round 9
// speedup vs baseline: 4.4107x; 1.0223x over previous
#include <cuda_runtime.h>
#include <cuda_bf16.h>
#include <cstdint>
#include <math.h>

// Problem constants
#define BB 16
#define NN 1024
#define CC 768
#define HH 12
#define HD 64

// ---------------------------------------------------------------------------
// Device-global scratch: split bf16 planes (hi + lo residual)
// ---------------------------------------------------------------------------
__device__ __nv_bfloat16 g_xs_h[(size_t)BB * NN * CC];
__device__ __nv_bfloat16 g_xs_l[(size_t)BB * NN * CC];
__device__ __nv_bfloat16 g_wq_h[(size_t)3 * CC * CC];
__device__ __nv_bfloat16 g_wq_l[(size_t)3 * CC * CC];
__device__ __nv_bfloat16 g_wp_h[(size_t)CC * CC];
__device__ __nv_bfloat16 g_wp_l[(size_t)CC * CC];
__device__ __nv_bfloat16 g_qkv_h[(size_t)3 * BB * HH * NN * HD];  // [3][B][H][N][HD]
__device__ __nv_bfloat16 g_qkv_l[(size_t)3 * BB * HH * NN * HD];
__device__ __nv_bfloat16 g_att_h[(size_t)BB * NN * CC];           // [B][N][C]
__device__ __nv_bfloat16 g_att_l[(size_t)BB * NN * CC];

// ===========================================================================
// Helpers (plain sm_80+ PTX)
// ===========================================================================
__device__ __forceinline__ uint32_t smem_u32(const void* p) {
    uint32_t a;
    asm("{ .reg .u64 t; cvta.to.shared.u64 t, %1; cvt.u32.u64 %0, t; }"
        : "=r"(a) : "l"(p));
    return a;
}
__device__ __forceinline__ void ldm_x4(uint32_t& r0, uint32_t& r1,
                                       uint32_t& r2, uint32_t& r3, uint32_t addr) {
    asm volatile("ldmatrix.sync.aligned.m8n8.x4.shared.b16 {%0,%1,%2,%3}, [%4];"
                 : "=r"(r0), "=r"(r1), "=r"(r2), "=r"(r3) : "r"(addr));
}
__device__ __forceinline__ void ldm_x4_t(uint32_t& r0, uint32_t& r1,
                                         uint32_t& r2, uint32_t& r3, uint32_t addr) {
    asm volatile("ldmatrix.sync.aligned.m8n8.x4.trans.shared.b16 {%0,%1,%2,%3}, [%4];"
                 : "=r"(r0), "=r"(r1), "=r"(r2), "=r"(r3) : "r"(addr));
}
__device__ __forceinline__ void mma_bf16(float* c, const uint32_t* a,
                                         uint32_t b0, uint32_t b1) {
    asm volatile(
        "mma.sync.aligned.m16n8k16.row.col.f32.bf16.bf16.f32 "
        "{%0,%1,%2,%3}, {%4,%5,%6,%7}, {%8,%9}, {%0,%1,%2,%3};"
        : "+f"(c[0]), "+f"(c[1]), "+f"(c[2]), "+f"(c[3])
        : "r"(a[0]), "r"(a[1]), "r"(a[2]), "r"(a[3]), "r"(b0), "r"(b1));
}
__device__ __forceinline__ uint32_t pack_bf(__nv_bfloat16 a, __nv_bfloat16 b) {
    uint32_t ua = (uint32_t)__bfloat16_as_ushort(a);
    uint32_t ub = (uint32_t)__bfloat16_as_ushort(b);
    return ua | (ub << 16);
}
__device__ __forceinline__ void bf_split(float x, __nv_bfloat16& h, __nv_bfloat16& l) {
    h = __float2bfloat16(x);
    l = __float2bfloat16(x - __bfloat162float(h));
}
__device__ __forceinline__ void cp_async16(uint32_t dst, const void* src) {
    asm volatile("cp.async.cg.shared.global [%0], [%1], 16;" :: "r"(dst), "l"(src));
}
#define CP_COMMIT() asm volatile("cp.async.commit_group;" ::: "memory")
#define CP_WAIT1()  asm volatile("cp.async.wait_group 1;" ::: "memory")

// ===========================================================================
// Split kernel: fp32 -> (hi, lo) bf16 planes
// ===========================================================================
__global__ void split_kernel(const float* __restrict__ src,
                             __nv_bfloat16* __restrict__ hi,
                             __nv_bfloat16* __restrict__ lo, int n4)
{
    int i = blockIdx.x * blockDim.x + threadIdx.x;
    if (i >= n4) return;
    float4 v = ((const float4*)src)[i];
    __nv_bfloat16 h0, h1, h2, h3, l0, l1, l2, l3;
    bf_split(v.x, h0, l0); bf_split(v.y, h1, l1);
    bf_split(v.z, h2, l2); bf_split(v.w, h3, l3);
    ((uint2*)hi)[i] = make_uint2(pack_bf(h0, h1), pack_bf(h2, h3));
    ((uint2*)lo)[i] = make_uint2(pack_bf(l0, l1), pack_bf(l2, l3));
}

// ===========================================================================
// bf16 mma.sync GEMM (3-term split), 64x64 warp tiles for smem-traffic cut.
// Block tile 128x256, BK=32, 256 threads = 8 warps (2m x 4n), 2-stage cp.async.
// MODE 0: epilogue splits + scatters into g_qkv_h/l planes.
// MODE 1: epilogue adds bias, writes fp32 Cout.
// ===========================================================================
#define BM 128
#define BN 256
#define BK 32
#define STR 40
#define A_PL (BM * STR * 2)              // 10240 B per A plane
#define B_PL (BN * STR * 2)              // 20480 B per B plane
#define OFF_AH 0
#define OFF_AL (A_PL)
#define OFF_BH (2 * A_PL)
#define OFF_BL (2 * A_PL + B_PL)
#define STAGE_B (2 * A_PL + 2 * B_PL)    // 61440
#define SM_GEMM (2 * STAGE_B)            // 122880

template <int MODE>
__global__ __launch_bounds__(256) void tc_gemm(
    const __nv_bfloat16* __restrict__ Ah_g, const __nv_bfloat16* __restrict__ Al_g,
    const __nv_bfloat16* __restrict__ Wh_g, const __nv_bfloat16* __restrict__ Wl_g,
    const float* __restrict__ bias, float* __restrict__ Cout, int K)
{
    extern __shared__ __align__(128) char dsm[];
    const uint32_t sb = smem_u32(dsm);

    const int t    = threadIdx.x;
    const int wid  = t >> 5;
    const int lane = t & 31;
    const int m0   = blockIdx.y * BM;
    const int n0   = blockIdx.x * BN;

    const int warp_m = (wid & 1) * 64;       // 2 warp-rows
    const int warp_n = (wid >> 1) * 64;      // 4 warp-cols
    const int rsel = lane & 15;
    const int ksel = (lane >> 4) * 8;

    auto load_stage = [&](int ck, int st) {
        const int k0 = ck * BK;
        const uint32_t base = sb + st * STAGE_B;
        // A: 512 chunks of 16B per plane-pair loop (128 rows x 4 cols)
#pragma unroll
        for (int i = 0; i < 2; ++i) {
            int idx = t + 256 * i;
            int r = idx >> 2, c = idx & 3;
            uint32_t doff = (uint32_t)(r * STR + c * 8) * 2;
            cp_async16(base + OFF_AH + doff, Ah_g + (size_t)(m0 + r) * K + k0 + c * 8);
            cp_async16(base + OFF_AL + doff, Al_g + (size_t)(m0 + r) * K + k0 + c * 8);
        }
        // B: 1024 chunks per plane (256 rows x 4 cols)
#pragma unroll
        for (int i = 0; i < 4; ++i) {
            int idx = t + 256 * i;
            int r = idx >> 2, c = idx & 3;
            uint32_t doff = (uint32_t)(r * STR + c * 8) * 2;
            cp_async16(base + OFF_BH + doff, Wh_g + (size_t)(n0 + r) * K + k0 + c * 8);
            cp_async16(base + OFF_BL + doff, Wl_g + (size_t)(n0 + r) * K + k0 + c * 8);
        }
    };

    float acc[4][8][4];
#pragma unroll
    for (int i = 0; i < 4; ++i)
#pragma unroll
        for (int j = 0; j < 8; ++j)
#pragma unroll
            for (int k = 0; k < 4; ++k) acc[i][j][k] = 0.f;

    const int nchunks = K / BK;   // 24
    load_stage(0, 0);
    CP_COMMIT();

    for (int ck = 0; ck < nchunks; ++ck) {
        if (ck + 1 < nchunks) load_stage(ck + 1, (ck + 1) & 1);
        CP_COMMIT();
        CP_WAIT1();
        __syncthreads();

        const uint32_t stb = sb + (ck & 1) * STAGE_B;
        const uint32_t sAh = stb + OFF_AH, sAl = stb + OFF_AL;
        const uint32_t sBh = stb + OFF_BH, sBl = stb + OFF_BL;

#pragma unroll
        for (int ks = 0; ks < 2; ++ks) {
            const int kb = ks * 16 + ksel;
            // A fragments for all 4 mt (hi + lo)
            uint32_t ah[4][4], al[4][4];
#pragma unroll
            for (int mt = 0; mt < 4; ++mt) {
                uint32_t aoff = (uint32_t)((warp_m + mt * 16 + rsel) * STR + kb) * 2;
                ldm_x4(ah[mt][0], ah[mt][1], ah[mt][2], ah[mt][3], sAh + aoff);
                ldm_x4(al[mt][0], al[mt][1], al[mt][2], al[mt][3], sAl + aoff);
            }
            // B in 4 groups of 16 n-rows
#pragma unroll
            for (int ntt = 0; ntt < 4; ++ntt) {
                uint32_t boff = (uint32_t)((warp_n + ntt * 16 + rsel) * STR + kb) * 2;
                uint32_t bh[4], bl[4];
                ldm_x4(bh[0], bh[1], bh[2], bh[3], sBh + boff);
                ldm_x4(bl[0], bl[1], bl[2], bl[3], sBl + boff);
#pragma unroll
                for (int mt = 0; mt < 4; ++mt) {
#pragma unroll
                    for (int sub = 0; sub < 2; ++sub) {
                        float* c = acc[mt][ntt * 2 + sub];
                        mma_bf16(c, ah[mt], bh[sub], bh[2 + sub]);
                        mma_bf16(c, ah[mt], bl[sub], bl[2 + sub]);
                        mma_bf16(c, al[mt], bh[sub], bh[2 + sub]);
                    }
                }
            }
        }
        __syncthreads();
    }

    // ---- epilogue ----
    const int cr = lane >> 2;
    const int cc = (lane & 3) * 2;
#pragma unroll
    for (int mt = 0; mt < 4; ++mt) {
#pragma unroll
        for (int nt = 0; nt < 8; ++nt) {
            int jr = n0 + warp_n + nt * 8 + cc;
#pragma unroll
            for (int half = 0; half < 2; ++half) {
                int m = m0 + warp_m + mt * 16 + cr + half * 8;
                float e0 = acc[mt][nt][half * 2 + 0];
                float e1 = acc[mt][nt][half * 2 + 1];
                if (MODE == 0) {
                    int b = m >> 10, n = m & 1023;
                    int s = jr / CC;
                    int rr = jr - s * CC;
                    int h = rr >> 6, d = rr & 63;
                    size_t idx = ((((size_t)s * BB + b) * HH + h) * NN + n) * HD + d;
                    __nv_bfloat16 h0, h1, l0, l1;
                    bf_split(e0, h0, l0); bf_split(e1, h1, l1);
                    *(uint32_t*)&g_qkv_h[idx] = pack_bf(h0, h1);
                    *(uint32_t*)&g_qkv_l[idx] = pack_bf(l0, l1);
                } else {
                    float2 bv = *(const float2*)(bias + jr);
                    float* dst = &Cout[(size_t)m * CC + jr];
                    *(float2*)dst = make_float2(e0 + bv.x, e1 + bv.y);
                }
            }
        }
    }
}

// ===========================================================================
// Flash attention, mma.sync bf16 3-term split, conversion-free staging.
// (unchanged from round 8)
// ===========================================================================
#define QSTR 72
#define ATILE (128 * QSTR * 2)
#define SA_QH 0
#define SA_QL (1 * ATILE)
#define SA_KH (2 * ATILE)
#define SA_KL (3 * ATILE)
#define SA_VH (4 * ATILE)
#define SA_VL (5 * ATILE)
#define SA_POL (6 * ATILE)
#define SA_TOT (6 * ATILE + 4096)
#define ASCALE 0.125f

__global__ __launch_bounds__(256, 1) void attn_mma(const float* __restrict__ policy)
{
    extern __shared__ __align__(16) char smb[];
    __nv_bfloat16* Qh = (__nv_bfloat16*)(smb + SA_QH);
    __nv_bfloat16* Ql = (__nv_bfloat16*)(smb + SA_QL);
    __nv_bfloat16* Kh = (__nv_bfloat16*)(smb + SA_KH);
    __nv_bfloat16* Kl = (__nv_bfloat16*)(smb + SA_KL);
    __nv_bfloat16* Vh = (__nv_bfloat16*)(smb + SA_VH);
    __nv_bfloat16* Vl = (__nv_bfloat16*)(smb + SA_VL);
    float*        POL = (float*)(smb + SA_POL);

    const int qt = blockIdx.x;
    const int bh = blockIdx.y;
    const int b  = bh / HH;
    const int h  = bh - b * HH;
    const int t    = threadIdx.x;
    const int wid  = t >> 5;
    const int lane = t & 31;
    const int rsel = lane & 15;
    const int ksel = (lane >> 4) * 8;
    const int m0 = qt * 128;

    const size_t plane = (size_t)NN * HD;
    const size_t hoff  = ((size_t)b * HH + h) * plane;
    const __nv_bfloat16* Qg_h = g_qkv_h + hoff + (size_t)m0 * HD;
    const __nv_bfloat16* Qg_l = g_qkv_l + hoff + (size_t)m0 * HD;
    const __nv_bfloat16* Kg_h = g_qkv_h + (size_t)BB * HH * plane + hoff;
    const __nv_bfloat16* Kg_l = g_qkv_l + (size_t)BB * HH * plane + hoff;
    const __nv_bfloat16* Vg_h = g_qkv_h + 2 * (size_t)BB * HH * plane + hoff;
    const __nv_bfloat16* Vg_l = g_qkv_l + 2 * (size_t)BB * HH * plane + hoff;

    for (int j = t; j < NN; j += 256) POL[j] = policy[b * NN + j];
#pragma unroll
    for (int i = 0; i < 4; ++i) {
        int idx = t + 256 * i;
        int r = idx >> 3, c8 = (idx & 7) * 8;
        *(uint4*)(Qh + r * QSTR + c8) = *(const uint4*)(Qg_h + (size_t)r * HD + c8);
        *(uint4*)(Ql + r * QSTR + c8) = *(const uint4*)(Qg_l + (size_t)r * HD + c8);
    }
    __syncthreads();

    const uint32_t sQh = smem_u32(Qh), sQl = smem_u32(Ql);
    const uint32_t sKh = smem_u32(Kh), sKl = smem_u32(Kl);
    const uint32_t sVh = smem_u32(Vh), sVl = smem_u32(Vl);

    uint32_t qh[4][4], ql[4][4];
    {
        int qrow = wid * 16 + rsel;
#pragma unroll
        for (int ks = 0; ks < 4; ++ks) {
            uint32_t off = (uint32_t)(qrow * QSTR + ks * 16 + ksel) * 2;
            ldm_x4(qh[ks][0], qh[ks][1], qh[ks][2], qh[ks][3], sQh + off);
            ldm_x4(ql[ks][0], ql[ks][1], ql[ks][2], ql[ks][3], sQl + off);
        }
    }

    float o[8][4];
#pragma unroll
    for (int i = 0; i < 8; ++i)
#pragma unroll
        for (int j = 0; j < 4; ++j) o[i][j] = 0.f;
    float l0 = 0.f, l1 = 0.f;
    float mm0 = -1e30f, mm1 = -1e30f;
    const int g0 = m0 + wid * 16 + (lane >> 2);
    const int g1 = g0 + 8;

    const int v_key8 = ((lane >> 3) & 1) * 8 + (lane & 7);
    const int v_d8   = (lane >> 4) * 8;

    for (int kv = 0; kv < 8; ++kv) {
        __syncthreads();

#pragma unroll
        for (int i = 0; i < 4; ++i) {
            int idx = t + 256 * i;
            int r = idx >> 3, c8 = (idx & 7) * 8;
            size_t gsrc = (size_t)(kv * 128 + r) * HD + c8;
            int doff = r * QSTR + c8;
            *(uint4*)(Kh + doff) = *(const uint4*)(Kg_h + gsrc);
            *(uint4*)(Kl + doff) = *(const uint4*)(Kg_l + gsrc);
            *(uint4*)(Vh + doff) = *(const uint4*)(Vg_h + gsrc);
            *(uint4*)(Vl + doff) = *(const uint4*)(Vg_l + gsrc);
        }
        __syncthreads();

        float s[16][4];
#pragma unroll
        for (int i = 0; i < 16; ++i)
#pragma unroll
            for (int j = 0; j < 4; ++j) s[i][j] = 0.f;

#pragma unroll
        for (int kb = 0; kb < 8; ++kb) {
#pragma unroll
            for (int ks = 0; ks < 4; ++ks) {
                uint32_t off = (uint32_t)((kb * 16 + rsel) * QSTR + ks * 16 + ksel) * 2;
                uint32_t kh[4], kl[4];
                ldm_x4(kh[0], kh[1], kh[2], kh[3], sKh + off);
                ldm_x4(kl[0], kl[1], kl[2], kl[3], sKl + off);
                mma_bf16(s[2 * kb + 0], qh[ks], kh[0], kh[2]);
                mma_bf16(s[2 * kb + 0], qh[ks], kl[0], kl[2]);
                mma_bf16(s[2 * kb + 0], ql[ks], kh[0], kh[2]);
                mma_bf16(s[2 * kb + 1], qh[ks], kh[1], kh[3]);
                mma_bf16(s[2 * kb + 1], qh[ks], kl[1], kl[3]);
                mma_bf16(s[2 * kb + 1], ql[ks], kh[1], kh[3]);
            }
        }

        float mx0 = -1e30f, mx1 = -1e30f;
#pragma unroll
        for (int nt = 0; nt < 16; ++nt) {
            mx0 = fmaxf(mx0, fmaxf(s[nt][0], s[nt][1]));
            mx1 = fmaxf(mx1, fmaxf(s[nt][2], s[nt][3]));
        }
        mx0 = fmaxf(mx0, __shfl_xor_sync(0xffffffffu, mx0, 1));
        mx0 = fmaxf(mx0, __shfl_xor_sync(0xffffffffu, mx0, 2));
        mx1 = fmaxf(mx1, __shfl_xor_sync(0xffffffffu, mx1, 1));
        mx1 = fmaxf(mx1, __shfl_xor_sync(0xffffffffu, mx1, 2));

        float nm0 = fmaxf(mm0, mx0);
        float nm1 = fmaxf(mm1, mx1);
        float al0 = __expf((mm0 - nm0) * ASCALE);
        float al1 = __expf((mm1 - nm1) * ASCALE);
        mm0 = nm0; mm1 = nm1;
        l0 *= al0; l1 *= al1;
#pragma unroll
        for (int nt = 0; nt < 8; ++nt) {
            o[nt][0] *= al0; o[nt][1] *= al0;
            o[nt][2] *= al1; o[nt][3] *= al1;
        }

        const int jb0 = kv * 128 + 2 * (lane & 3);
        float sum0 = 0.f, sum1 = 0.f;
#pragma unroll
        for (int nt = 0; nt < 16; ++nt) {
            int j0 = jb0 + nt * 8;
            float w0 = (j0 == g0) ? 1.f : POL[j0];
            float w1 = (j0 + 1 == g0) ? 1.f : POL[j0 + 1];
            float w2 = (j0 == g1) ? 1.f : POL[j0];
            float w3 = (j0 + 1 == g1) ? 1.f : POL[j0 + 1];
            float p0 = __expf((s[nt][0] - nm0) * ASCALE) * w0;
            float p1 = __expf((s[nt][1] - nm0) * ASCALE) * w1;
            float p2 = __expf((s[nt][2] - nm1) * ASCALE) * w2;
            float p3 = __expf((s[nt][3] - nm1) * ASCALE) * w3;
            sum0 += p0 + p1; sum1 += p2 + p3;
            s[nt][0] = p0; s[nt][1] = p1; s[nt][2] = p2; s[nt][3] = p3;
        }
        sum0 += __shfl_xor_sync(0xffffffffu, sum0, 1);
        sum0 += __shfl_xor_sync(0xffffffffu, sum0, 2);
        sum1 += __shfl_xor_sync(0xffffffffu, sum1, 1);
        sum1 += __shfl_xor_sync(0xffffffffu, sum1, 2);
        l0 += sum0; l1 += sum1;

#pragma unroll
        for (int kb = 0; kb < 8; ++kb) {
            __nv_bfloat16 hA, lA, hB, lB;
            uint32_t pah[4], pal[4];
            bf_split(s[2 * kb][0], hA, lA); bf_split(s[2 * kb][1], hB, lB);
            pah[0] = pack_bf(hA, hB); pal[0] = pack_bf(lA, lB);
            bf_split(s[2 * kb][2], hA, lA); bf_split(s[2 * kb][3], hB, lB);
            pah[1] = pack_bf(hA, hB); pal[1] = pack_bf(lA, lB);
            bf_split(s[2 * kb + 1][0], hA, lA); bf_split(s[2 * kb + 1][1], hB, lB);
            pah[2] = pack_bf(hA, hB); pal[2] = pack_bf(lA, lB);
            bf_split(s[2 * kb + 1][2], hA, lA); bf_split(s[2 * kb + 1][3], hB, lB);
            pah[3] = pack_bf(hA, hB); pal[3] = pack_bf(lA, lB);

            const int keyb = kb * 16 + v_key8;
#pragma unroll
            for (int dq = 0; dq < 4; ++dq) {
                uint32_t off = (uint32_t)(keyb * QSTR + dq * 16 + v_d8) * 2;
                uint32_t vh[4], vl[4];
                ldm_x4_t(vh[0], vh[1], vh[2], vh[3], sVh + off);
                ldm_x4_t(vl[0], vl[1], vl[2], vl[3], sVl + off);
                mma_bf16(o[2 * dq + 0], pah, vh[0], vh[1]);
                mma_bf16(o[2 * dq + 0], pah, vl[0], vl[1]);
                mma_bf16(o[2 * dq + 0], pal, vh[0], vh[1]);
                mma_bf16(o[2 * dq + 1], pah, vh[2], vh[3]);
                mma_bf16(o[2 * dq + 1], pah, vl[2], vl[3]);
                mma_bf16(o[2 * dq + 1], pal, vh[2], vh[3]);
            }
        }
    }

    const float inv0 = 1.0f / (l0 + 1e-6f);
    const float inv1 = 1.0f / (l1 + 1e-6f);
    const int d0 = (lane & 3) * 2;
#pragma unroll
    for (int nt = 0; nt < 8; ++nt) {
        int d = nt * 8 + d0;
        size_t i0 = ((size_t)b * NN + g0) * CC + h * HD + d;
        size_t i1 = ((size_t)b * NN + g1) * CC + h * HD + d;
        __nv_bfloat16 h0, h1, lo0, lo1;
        bf_split(o[nt][0] * inv0, h0, lo0); bf_split(o[nt][1] * inv0, h1, lo1);
        *(uint32_t*)&g_att_h[i0] = pack_bf(h0, h1);
        *(uint32_t*)&g_att_l[i0] = pack_bf(lo0, lo1);
        bf_split(o[nt][2] * inv1, h0, lo0); bf_split(o[nt][3] * inv1, h1, lo1);
        *(uint32_t*)&g_att_h[i1] = pack_bf(h0, h1);
        *(uint32_t*)&g_att_l[i1] = pack_bf(lo0, lo1);
    }
}

// ===========================================================================
// Launch
// ===========================================================================
extern "C" void kernel_launch(void* const* d_in, const int* in_sizes, int n_in,
                              void* d_out, int out_size)
{
    const float* x      = (const float*)d_in[0];   // [16, 1024, 768]
    const float* policy = (const float*)d_in[1];   // [16, 1024, 1]
    const float* w_qkv  = (const float*)d_in[2];   // [2304, 768]
    const float* w_proj = (const float*)d_in[3];   // [768, 768]
    const float* b_proj = (const float*)d_in[4];   // [768]
    float* out = (float*)d_out;                    // [16, 1024, 768]

    (void)in_sizes; (void)n_in; (void)out_size;

    cudaFuncSetAttribute(tc_gemm<0>, cudaFuncAttributeMaxDynamicSharedMemorySize, SM_GEMM);
    cudaFuncSetAttribute(tc_gemm<1>, cudaFuncAttributeMaxDynamicSharedMemorySize, SM_GEMM);
    cudaFuncSetAttribute(attn_mma, cudaFuncAttributeMaxDynamicSharedMemorySize, SA_TOT);

    __nv_bfloat16 *xs_h, *xs_l, *wq_h, *wq_l, *wp_h, *wp_l;
    cudaGetSymbolAddress((void**)&xs_h, g_xs_h);
    cudaGetSymbolAddress((void**)&xs_l, g_xs_l);
    cudaGetSymbolAddress((void**)&wq_h, g_wq_h);
    cudaGetSymbolAddress((void**)&wq_l, g_wq_l);
    cudaGetSymbolAddress((void**)&wp_h, g_wp_h);
    cudaGetSymbolAddress((void**)&wp_l, g_wp_l);

    // 1) pre-split inputs
    {
        int n4x = BB * NN * CC / 4;
        split_kernel<<<(n4x + 255) / 256, 256>>>(x, xs_h, xs_l, n4x);
        int n4q = 3 * CC * CC / 4;
        split_kernel<<<(n4q + 255) / 256, 256>>>(w_qkv, wq_h, wq_l, n4q);
        int n4p = CC * CC / 4;
        split_kernel<<<(n4p + 255) / 256, 256>>>(w_proj, wp_h, wp_l, n4p);
    }
    // 2) QKV GEMM -> split g_qkv planes
    {
        dim3 grid(2304 / BN, 16384 / BM);      // (9, 128)
        tc_gemm<0><<<grid, 256, SM_GEMM>>>(xs_h, xs_l, wq_h, wq_l, nullptr, nullptr, CC);
    }
    // 3) Flash attention -> split g_att planes
    {
        dim3 grid(8, BB * HH);
        attn_mma<<<grid, 256, SA_TOT>>>(policy);
    }
    // 4) Projection -> out (fp32 + bias)
    {
        __nv_bfloat16 *at_h, *at_l;
        cudaGetSymbolAddress((void**)&at_h, g_att_h);
        cudaGetSymbolAddress((void**)&at_l, g_att_l);
        dim3 grid(CC / BN, 16384 / BM);        // (3, 128)
        tc_gemm<1><<<grid, 256, SM_GEMM>>>(at_h, at_l, wp_h, wp_l, b_proj, out, CC);
    }
}

// round 10
// speedup vs baseline: 4.6609x; 1.0567x over previous
#include <cuda_runtime.h>
#include <cuda_bf16.h>
#include <cstdint>
#include <math.h>

// Problem constants
#define BB 16
#define NN 1024
#define CC 768
#define HH 12
#define HD 64

// ---------------------------------------------------------------------------
// Device-global scratch: split bf16 planes (hi + lo residual)
// ---------------------------------------------------------------------------
__device__ __nv_bfloat16 g_xs_h[(size_t)BB * NN * CC];
__device__ __nv_bfloat16 g_xs_l[(size_t)BB * NN * CC];
__device__ __nv_bfloat16 g_wq_h[(size_t)3 * CC * CC];
__device__ __nv_bfloat16 g_wq_l[(size_t)3 * CC * CC];
__device__ __nv_bfloat16 g_wp_h[(size_t)CC * CC];
__device__ __nv_bfloat16 g_wp_l[(size_t)CC * CC];
__device__ __nv_bfloat16 g_qkv_h[(size_t)3 * BB * HH * NN * HD];  // [3][B][H][N][HD]
__device__ __nv_bfloat16 g_qkv_l[(size_t)3 * BB * HH * NN * HD];
__device__ __nv_bfloat16 g_att_h[(size_t)BB * NN * CC];           // [B][N][C]
__device__ __nv_bfloat16 g_att_l[(size_t)BB * NN * CC];

// ===========================================================================
// Helpers (plain sm_80+ PTX)
// ===========================================================================
__device__ __forceinline__ uint32_t smem_u32(const void* p) {
    uint32_t a;
    asm("{ .reg .u64 t; cvta.to.shared.u64 t, %1; cvt.u32.u64 %0, t; }"
        : "=r"(a) : "l"(p));
    return a;
}
__device__ __forceinline__ void ldm_x4(uint32_t& r0, uint32_t& r1,
                                       uint32_t& r2, uint32_t& r3, uint32_t addr) {
    asm volatile("ldmatrix.sync.aligned.m8n8.x4.shared.b16 {%0,%1,%2,%3}, [%4];"
                 : "=r"(r0), "=r"(r1), "=r"(r2), "=r"(r3) : "r"(addr));
}
__device__ __forceinline__ void ldm_x4_t(uint32_t& r0, uint32_t& r1,
                                         uint32_t& r2, uint32_t& r3, uint32_t addr) {
    asm volatile("ldmatrix.sync.aligned.m8n8.x4.trans.shared.b16 {%0,%1,%2,%3}, [%4];"
                 : "=r"(r0), "=r"(r1), "=r"(r2), "=r"(r3) : "r"(addr));
}
__device__ __forceinline__ void mma_bf16(float* c, const uint32_t* a,
                                         uint32_t b0, uint32_t b1) {
    asm volatile(
        "mma.sync.aligned.m16n8k16.row.col.f32.bf16.bf16.f32 "
        "{%0,%1,%2,%3}, {%4,%5,%6,%7}, {%8,%9}, {%0,%1,%2,%3};"
        : "+f"(c[0]), "+f"(c[1]), "+f"(c[2]), "+f"(c[3])
        : "r"(a[0]), "r"(a[1]), "r"(a[2]), "r"(a[3]), "r"(b0), "r"(b1));
}
__device__ __forceinline__ uint32_t pack_bf(__nv_bfloat16 a, __nv_bfloat16 b) {
    uint32_t ua = (uint32_t)__bfloat16_as_ushort(a);
    uint32_t ub = (uint32_t)__bfloat16_as_ushort(b);
    return ua | (ub << 16);
}
__device__ __forceinline__ void bf_split(float x, __nv_bfloat16& h, __nv_bfloat16& l) {
    h = __float2bfloat16(x);
    l = __float2bfloat16(x - __bfloat162float(h));
}
__device__ __forceinline__ void cp_async16(uint32_t dst, const void* src) {
    asm volatile("cp.async.cg.shared.global [%0], [%1], 16;" :: "r"(dst), "l"(src));
}
#define CP_COMMIT() asm volatile("cp.async.commit_group;" ::: "memory")
#define CP_WAIT1()  asm volatile("cp.async.wait_group 1;" ::: "memory")
#define CP_WAIT0()  asm volatile("cp.async.wait_group 0;" ::: "memory")

// ===========================================================================
// Split kernel: fp32 -> (hi, lo) bf16 planes
// ===========================================================================
__global__ void split_kernel(const float* __restrict__ src,
                             __nv_bfloat16* __restrict__ hi,
                             __nv_bfloat16* __restrict__ lo, int n4)
{
    int i = blockIdx.x * blockDim.x + threadIdx.x;
    if (i >= n4) return;
    float4 v = ((const float4*)src)[i];
    __nv_bfloat16 h0, h1, h2, h3, l0, l1, l2, l3;
    bf_split(v.x, h0, l0); bf_split(v.y, h1, l1);
    bf_split(v.z, h2, l2); bf_split(v.w, h3, l3);
    ((uint2*)hi)[i] = make_uint2(pack_bf(h0, h1), pack_bf(h2, h3));
    ((uint2*)lo)[i] = make_uint2(pack_bf(l0, l1), pack_bf(l2, l3));
}

// ===========================================================================
// bf16 mma.sync GEMM (3-term split).
// Block 128x256, BK=32, 512 threads = 16 warps (4m x 4n) of 32x64 tiles.
// 2-stage cp.async double buffer. MODE 0: scatter split planes to g_qkv.
// MODE 1: +bias, fp32 Cout.
// ===========================================================================
#define BM 128
#define BN 256
#define BK 32
#define STR 40
#define A_PL (BM * STR * 2)              // 10240 B per A plane
#define B_PL (BN * STR * 2)              // 20480 B per B plane
#define OFF_AH 0
#define OFF_AL (A_PL)
#define OFF_BH (2 * A_PL)
#define OFF_BL (2 * A_PL + B_PL)
#define STAGE_B (2 * A_PL + 2 * B_PL)    // 61440
#define SM_GEMM (2 * STAGE_B)            // 122880

template <int MODE>
__global__ __launch_bounds__(512) void tc_gemm(
    const __nv_bfloat16* __restrict__ Ah_g, const __nv_bfloat16* __restrict__ Al_g,
    const __nv_bfloat16* __restrict__ Wh_g, const __nv_bfloat16* __restrict__ Wl_g,
    const float* __restrict__ bias, float* __restrict__ Cout, int K)
{
    extern __shared__ __align__(128) char dsm[];
    const uint32_t sb = smem_u32(dsm);

    const int t    = threadIdx.x;
    const int wid  = t >> 5;
    const int lane = t & 31;
    const int m0   = blockIdx.y * BM;
    const int n0   = blockIdx.x * BN;

    const int warp_m = (wid & 3) * 32;       // 4 warp-rows of 32
    const int warp_n = (wid >> 2) * 64;      // 4 warp-cols of 64
    const int rsel = lane & 15;
    const int ksel = (lane >> 4) * 8;

    auto load_stage = [&](int ck, int st) {
        const int k0 = ck * BK;
        const uint32_t base = sb + st * STAGE_B;
        // A: 512 chunks of 16B per plane (128 rows x 4 cols), 1 per thread
        {
            int r = t >> 2, c = t & 3;
            uint32_t doff = (uint32_t)(r * STR + c * 8) * 2;
            cp_async16(base + OFF_AH + doff, Ah_g + (size_t)(m0 + r) * K + k0 + c * 8);
            cp_async16(base + OFF_AL + doff, Al_g + (size_t)(m0 + r) * K + k0 + c * 8);
        }
        // B: 1024 chunks per plane (256 rows x 4 cols), 2 per thread
#pragma unroll
        for (int i = 0; i < 2; ++i) {
            int idx = t + 512 * i;
            int r = idx >> 2, c = idx & 3;
            uint32_t doff = (uint32_t)(r * STR + c * 8) * 2;
            cp_async16(base + OFF_BH + doff, Wh_g + (size_t)(n0 + r) * K + k0 + c * 8);
            cp_async16(base + OFF_BL + doff, Wl_g + (size_t)(n0 + r) * K + k0 + c * 8);
        }
    };

    float acc[2][8][4];
#pragma unroll
    for (int i = 0; i < 2; ++i)
#pragma unroll
        for (int j = 0; j < 8; ++j)
#pragma unroll
            for (int k = 0; k < 4; ++k) acc[i][j][k] = 0.f;

    const int nchunks = K / BK;   // 24
    load_stage(0, 0);
    CP_COMMIT();

    for (int ck = 0; ck < nchunks; ++ck) {
        if (ck + 1 < nchunks) load_stage(ck + 1, (ck + 1) & 1);
        CP_COMMIT();
        CP_WAIT1();
        __syncthreads();

        const uint32_t stb = sb + (ck & 1) * STAGE_B;
        const uint32_t sAh = stb + OFF_AH, sAl = stb + OFF_AL;
        const uint32_t sBh = stb + OFF_BH, sBl = stb + OFF_BL;

#pragma unroll
        for (int ks = 0; ks < 2; ++ks) {
            const int kb = ks * 16 + ksel;
            uint32_t ah[2][4], al[2][4];
#pragma unroll
            for (int mt = 0; mt < 2; ++mt) {
                uint32_t aoff = (uint32_t)((warp_m + mt * 16 + rsel) * STR + kb) * 2;
                ldm_x4(ah[mt][0], ah[mt][1], ah[mt][2], ah[mt][3], sAh + aoff);
                ldm_x4(al[mt][0], al[mt][1], al[mt][2], al[mt][3], sAl + aoff);
            }
#pragma unroll
            for (int ntt = 0; ntt < 4; ++ntt) {
                uint32_t boff = (uint32_t)((warp_n + ntt * 16 + rsel) * STR + kb) * 2;
                uint32_t bh[4], bl[4];
                ldm_x4(bh[0], bh[1], bh[2], bh[3], sBh + boff);
                ldm_x4(bl[0], bl[1], bl[2], bl[3], sBl + boff);
#pragma unroll
                for (int mt = 0; mt < 2; ++mt) {
#pragma unroll
                    for (int sub = 0; sub < 2; ++sub) {
                        float* c = acc[mt][ntt * 2 + sub];
                        mma_bf16(c, ah[mt], bh[sub], bh[2 + sub]);
                        mma_bf16(c, ah[mt], bl[sub], bl[2 + sub]);
                        mma_bf16(c, al[mt], bh[sub], bh[2 + sub]);
                    }
                }
            }
        }
        __syncthreads();
    }

    // ---- epilogue ----
    const int cr = lane >> 2;
    const int cc = (lane & 3) * 2;
#pragma unroll
    for (int mt = 0; mt < 2; ++mt) {
#pragma unroll
        for (int nt = 0; nt < 8; ++nt) {
            int jr = n0 + warp_n + nt * 8 + cc;
#pragma unroll
            for (int half = 0; half < 2; ++half) {
                int m = m0 + warp_m + mt * 16 + cr + half * 8;
                float e0 = acc[mt][nt][half * 2 + 0];
                float e1 = acc[mt][nt][half * 2 + 1];
                if (MODE == 0) {
                    int b = m >> 10, n = m & 1023;
                    int s = jr / CC;
                    int rr = jr - s * CC;
                    int h = rr >> 6, d = rr & 63;
                    size_t idx = ((((size_t)s * BB + b) * HH + h) * NN + n) * HD + d;
                    __nv_bfloat16 h0, h1, l0, l1;
                    bf_split(e0, h0, l0); bf_split(e1, h1, l1);
                    *(uint32_t*)&g_qkv_h[idx] = pack_bf(h0, h1);
                    *(uint32_t*)&g_qkv_l[idx] = pack_bf(l0, l1);
                } else {
                    float2 bv = *(const float2*)(bias + jr);
                    float* dst = &Cout[(size_t)m * CC + jr];
                    *(float2*)dst = make_float2(e0 + bv.x, e1 + bv.y);
                }
            }
        }
    }
}

// ===========================================================================
// Flash attention, mma.sync bf16 3-term split, cp.async double-buffered KV.
// CTA: 128 q-rows x head, 256 threads = 8 warps x 16 q-rows. 8 kv tiles of 128.
// ===========================================================================
#define QSTR 72
#define APL (128 * QSTR * 2)          // 18432 B per plane tile
#define SA_QH 0
#define SA_QL (APL)
#define SA_ST (2 * APL)               // KV stages base
#define ST_KH 0
#define ST_KL (APL)
#define ST_VH (2 * APL)
#define ST_VL (3 * APL)
#define ST_SZ (4 * APL)               // 73728 per stage
#define SA_POL (SA_ST + 2 * ST_SZ)    // 184320
#define SA_TOT (SA_POL + 4096)        // 188416
#define ASCALE 0.125f

__global__ __launch_bounds__(256, 1) void attn_mma(const float* __restrict__ policy)
{
    extern __shared__ __align__(16) char smb[];
    __nv_bfloat16* Qh = (__nv_bfloat16*)(smb + SA_QH);
    __nv_bfloat16* Ql = (__nv_bfloat16*)(smb + SA_QL);
    float*        POL = (float*)(smb + SA_POL);
    const uint32_t sb = smem_u32(smb);

    const int qt = blockIdx.x;
    const int bh = blockIdx.y;
    const int b  = bh / HH;
    const int h  = bh - b * HH;
    const int t    = threadIdx.x;
    const int wid  = t >> 5;
    const int lane = t & 31;
    const int rsel = lane & 15;
    const int ksel = (lane >> 4) * 8;
    const int m0 = qt * 128;

    const size_t plane = (size_t)NN * HD;
    const size_t hoff  = ((size_t)b * HH + h) * plane;
    const __nv_bfloat16* Qg_h = g_qkv_h + hoff + (size_t)m0 * HD;
    const __nv_bfloat16* Qg_l = g_qkv_l + hoff + (size_t)m0 * HD;
    const __nv_bfloat16* Kg_h = g_qkv_h + (size_t)BB * HH * plane + hoff;
    const __nv_bfloat16* Kg_l = g_qkv_l + (size_t)BB * HH * plane + hoff;
    const __nv_bfloat16* Vg_h = g_qkv_h + 2 * (size_t)BB * HH * plane + hoff;
    const __nv_bfloat16* Vg_l = g_qkv_l + 2 * (size_t)BB * HH * plane + hoff;

    auto prefetch_kv = [&](int kv, int st) {
        const uint32_t base = sb + SA_ST + st * ST_SZ;
#pragma unroll
        for (int i = 0; i < 4; ++i) {
            int idx = t + 256 * i;
            int r = idx >> 3, c8 = (idx & 7) * 8;
            size_t gsrc = (size_t)(kv * 128 + r) * HD + c8;
            uint32_t doff = (uint32_t)(r * QSTR + c8) * 2;
            cp_async16(base + ST_KH + doff, Kg_h + gsrc);
            cp_async16(base + ST_KL + doff, Kg_l + gsrc);
            cp_async16(base + ST_VH + doff, Vg_h + gsrc);
            cp_async16(base + ST_VL + doff, Vg_l + gsrc);
        }
    };

    // kick off KV tile 0 before staging Q (overlap)
    prefetch_kv(0, 0);
    CP_COMMIT();

    for (int j = t; j < NN; j += 256) POL[j] = policy[b * NN + j];
#pragma unroll
    for (int i = 0; i < 4; ++i) {
        int idx = t + 256 * i;
        int r = idx >> 3, c8 = (idx & 7) * 8;
        *(uint4*)(Qh + r * QSTR + c8) = *(const uint4*)(Qg_h + (size_t)r * HD + c8);
        *(uint4*)(Ql + r * QSTR + c8) = *(const uint4*)(Qg_l + (size_t)r * HD + c8);
    }
    __syncthreads();

    const uint32_t sQh = sb + SA_QH, sQl = sb + SA_QL;

    uint32_t qh[4][4], ql[4][4];
    {
        int qrow = wid * 16 + rsel;
#pragma unroll
        for (int ks = 0; ks < 4; ++ks) {
            uint32_t off = (uint32_t)(qrow * QSTR + ks * 16 + ksel) * 2;
            ldm_x4(qh[ks][0], qh[ks][1], qh[ks][2], qh[ks][3], sQh + off);
            ldm_x4(ql[ks][0], ql[ks][1], ql[ks][2], ql[ks][3], sQl + off);
        }
    }

    float o[8][4];
#pragma unroll
    for (int i = 0; i < 8; ++i)
#pragma unroll
        for (int j = 0; j < 4; ++j) o[i][j] = 0.f;
    float l0 = 0.f, l1 = 0.f;
    float mm0 = -1e30f, mm1 = -1e30f;
    const int g0 = m0 + wid * 16 + (lane >> 2);
    const int g1 = g0 + 8;

    const int v_key8 = ((lane >> 3) & 1) * 8 + (lane & 7);
    const int v_d8   = (lane >> 4) * 8;

    for (int kv = 0; kv < 8; ++kv) {
        CP_WAIT0();
        __syncthreads();     // stage kv ready; all warps done with stage kv-1

        if (kv + 1 < 8) { prefetch_kv(kv + 1, (kv + 1) & 1); CP_COMMIT(); }

        const uint32_t stb = sb + SA_ST + (kv & 1) * ST_SZ;
        const uint32_t sKh = stb + ST_KH, sKl = stb + ST_KL;
        const uint32_t sVh = stb + ST_VH, sVl = stb + ST_VL;

        float s[16][4];
#pragma unroll
        for (int i = 0; i < 16; ++i)
#pragma unroll
            for (int j = 0; j < 4; ++j) s[i][j] = 0.f;

#pragma unroll
        for (int kb = 0; kb < 8; ++kb) {
#pragma unroll
            for (int ks = 0; ks < 4; ++ks) {
                uint32_t off = (uint32_t)((kb * 16 + rsel) * QSTR + ks * 16 + ksel) * 2;
                uint32_t kh[4], kl[4];
                ldm_x4(kh[0], kh[1], kh[2], kh[3], sKh + off);
                ldm_x4(kl[0], kl[1], kl[2], kl[3], sKl + off);
                mma_bf16(s[2 * kb + 0], qh[ks], kh[0], kh[2]);
                mma_bf16(s[2 * kb + 0], qh[ks], kl[0], kl[2]);
                mma_bf16(s[2 * kb + 0], ql[ks], kh[0], kh[2]);
                mma_bf16(s[2 * kb + 1], qh[ks], kh[1], kh[3]);
                mma_bf16(s[2 * kb + 1], qh[ks], kl[1], kl[3]);
                mma_bf16(s[2 * kb + 1], ql[ks], kh[1], kh[3]);
            }
        }

        float mx0 = -1e30f, mx1 = -1e30f;
#pragma unroll
        for (int nt = 0; nt < 16; ++nt) {
            mx0 = fmaxf(mx0, fmaxf(s[nt][0], s[nt][1]));
            mx1 = fmaxf(mx1, fmaxf(s[nt][2], s[nt][3]));
        }
        mx0 = fmaxf(mx0, __shfl_xor_sync(0xffffffffu, mx0, 1));
        mx0 = fmaxf(mx0, __shfl_xor_sync(0xffffffffu, mx0, 2));
        mx1 = fmaxf(mx1, __shfl_xor_sync(0xffffffffu, mx1, 1));
        mx1 = fmaxf(mx1, __shfl_xor_sync(0xffffffffu, mx1, 2));

        float nm0 = fmaxf(mm0, mx0);
        float nm1 = fmaxf(mm1, mx1);
        float al0 = __expf((mm0 - nm0) * ASCALE);
        float al1 = __expf((mm1 - nm1) * ASCALE);
        mm0 = nm0; mm1 = nm1;
        l0 *= al0; l1 *= al1;
#pragma unroll
        for (int nt = 0; nt < 8; ++nt) {
            o[nt][0] *= al0; o[nt][1] *= al0;
            o[nt][2] *= al1; o[nt][3] *= al1;
        }

        const int jb0 = kv * 128 + 2 * (lane & 3);
        float sum0 = 0.f, sum1 = 0.f;
#pragma unroll
        for (int nt = 0; nt < 16; ++nt) {
            int j0 = jb0 + nt * 8;
            float w0 = (j0 == g0) ? 1.f : POL[j0];
            float w1 = (j0 + 1 == g0) ? 1.f : POL[j0 + 1];
            float w2 = (j0 == g1) ? 1.f : POL[j0];
            float w3 = (j0 + 1 == g1) ? 1.f : POL[j0 + 1];
            float p0 = __expf((s[nt][0] - nm0) * ASCALE) * w0;
            float p1 = __expf((s[nt][1] - nm0) * ASCALE) * w1;
            float p2 = __expf((s[nt][2] - nm1) * ASCALE) * w2;
            float p3 = __expf((s[nt][3] - nm1) * ASCALE) * w3;
            sum0 += p0 + p1; sum1 += p2 + p3;
            s[nt][0] = p0; s[nt][1] = p1; s[nt][2] = p2; s[nt][3] = p3;
        }
        sum0 += __shfl_xor_sync(0xffffffffu, sum0, 1);
        sum0 += __shfl_xor_sync(0xffffffffu, sum0, 2);
        sum1 += __shfl_xor_sync(0xffffffffu, sum1, 1);
        sum1 += __shfl_xor_sync(0xffffffffu, sum1, 2);
        l0 += sum0; l1 += sum1;

#pragma unroll
        for (int kb = 0; kb < 8; ++kb) {
            __nv_bfloat16 hA, lA, hB, lB;
            uint32_t pah[4], pal[4];
            bf_split(s[2 * kb][0], hA, lA); bf_split(s[2 * kb][1], hB, lB);
            pah[0] = pack_bf(hA, hB); pal[0] = pack_bf(lA, lB);
            bf_split(s[2 * kb][2], hA, lA); bf_split(s[2 * kb][3], hB, lB);
            pah[1] = pack_bf(hA, hB); pal[1] = pack_bf(lA, lB);
            bf_split(s[2 * kb + 1][0], hA, lA); bf_split(s[2 * kb + 1][1], hB, lB);
            pah[2] = pack_bf(hA, hB); pal[2] = pack_bf(lA, lB);
            bf_split(s[2 * kb + 1][2], hA, lA); bf_split(s[2 * kb + 1][3], hB, lB);
            pah[3] = pack_bf(hA, hB); pal[3] = pack_bf(lA, lB);

            const int keyb = kb * 16 + v_key8;
#pragma unroll
            for (int dq = 0; dq < 4; ++dq) {
                uint32_t off = (uint32_t)(keyb * QSTR + dq * 16 + v_d8) * 2;
                uint32_t vh[4], vl[4];
                ldm_x4_t(vh[0], vh[1], vh[2], vh[3], sVh + off);
                ldm_x4_t(vl[0], vl[1], vl[2], vl[3], sVl + off);
                mma_bf16(o[2 * dq + 0], pah, vh[0], vh[1]);
                mma_bf16(o[2 * dq + 0], pah, vl[0], vl[1]);
                mma_bf16(o[2 * dq + 0], pal, vh[0], vh[1]);
                mma_bf16(o[2 * dq + 1], pah, vh[2], vh[3]);
                mma_bf16(o[2 * dq + 1], pah, vl[2], vl[3]);
                mma_bf16(o[2 * dq + 1], pal, vh[2], vh[3]);
            }
        }
    }

    const float inv0 = 1.0f / (l0 + 1e-6f);
    const float inv1 = 1.0f / (l1 + 1e-6f);
    const int d0 = (lane & 3) * 2;
#pragma unroll
    for (int nt = 0; nt < 8; ++nt) {
        int d = nt * 8 + d0;
        size_t i0 = ((size_t)b * NN + g0) * CC + h * HD + d;
        size_t i1 = ((size_t)b * NN + g1) * CC + h * HD + d;
        __nv_bfloat16 h0, h1, lo0, lo1;
        bf_split(o[nt][0] * inv0, h0, lo0); bf_split(o[nt][1] * inv0, h1, lo1);
        *(uint32_t*)&g_att_h[i0] = pack_bf(h0, h1);
        *(uint32_t*)&g_att_l[i0] = pack_bf(lo0, lo1);
        bf_split(o[nt][2] * inv1, h0, lo0); bf_split(o[nt][3] * inv1, h1, lo1);
        *(uint32_t*)&g_att_h[i1] = pack_bf(h0, h1);
        *(uint32_t*)&g_att_l[i1] = pack_bf(lo0, lo1);
    }
}

// ===========================================================================
// Launch
// ===========================================================================
extern "C" void kernel_launch(void* const* d_in, const int* in_sizes, int n_in,
                              void* d_out, int out_size)
{
    const float* x      = (const float*)d_in[0];   // [16, 1024, 768]
    const float* policy = (const float*)d_in[1];   // [16, 1024, 1]
    const float* w_qkv  = (const float*)d_in[2];   // [2304, 768]
    const float* w_proj = (const float*)d_in[3];   // [768, 768]
    const float* b_proj = (const float*)d_in[4];   // [768]
    float* out = (float*)d_out;                    // [16, 1024, 768]

    (void)in_sizes; (void)n_in; (void)out_size;

    cudaFuncSetAttribute(tc_gemm<0>, cudaFuncAttributeMaxDynamicSharedMemorySize, SM_GEMM);
    cudaFuncSetAttribute(tc_gemm<1>, cudaFuncAttributeMaxDynamicSharedMemorySize, SM_GEMM);
    cudaFuncSetAttribute(attn_mma, cudaFuncAttributeMaxDynamicSharedMemorySize, SA_TOT);

    __nv_bfloat16 *xs_h, *xs_l, *wq_h, *wq_l, *wp_h, *wp_l;
    cudaGetSymbolAddress((void**)&xs_h, g_xs_h);
    cudaGetSymbolAddress((void**)&xs_l, g_xs_l);
    cudaGetSymbolAddress((void**)&wq_h, g_wq_h);
    cudaGetSymbolAddress((void**)&wq_l, g_wq_l);
    cudaGetSymbolAddress((void**)&wp_h, g_wp_h);
    cudaGetSymbolAddress((void**)&wp_l, g_wp_l);

    // 1) pre-split inputs
    {
        int n4x = BB * NN * CC / 4;
        split_kernel<<<(n4x + 255) / 256, 256>>>(x, xs_h, xs_l, n4x);
        int n4q = 3 * CC * CC / 4;
        split_kernel<<<(n4q + 255) / 256, 256>>>(w_qkv, wq_h, wq_l, n4q);
        int n4p = CC * CC / 4;
        split_kernel<<<(n4p + 255) / 256, 256>>>(w_proj, wp_h, wp_l, n4p);
    }
    // 2) QKV GEMM -> split g_qkv planes
    {
        dim3 grid(2304 / BN, 16384 / BM);      // (9, 128)
        tc_gemm<0><<<grid, 512, SM_GEMM>>>(xs_h, xs_l, wq_h, wq_l, nullptr, nullptr, CC);
    }
    // 3) Flash attention -> split g_att planes
    {
        dim3 grid(8, BB * HH);
        attn_mma<<<grid, 256, SA_TOT>>>(policy);
    }
    // 4) Projection -> out (fp32 + bias)
    {
        __nv_bfloat16 *at_h, *at_l;
        cudaGetSymbolAddress((void**)&at_h, g_att_h);
        cudaGetSymbolAddress((void**)&at_l, g_att_l);
        dim3 grid(CC / BN, 16384 / BM);        // (3, 128)
        tc_gemm<1><<<grid, 512, SM_GEMM>>>(at_h, at_l, wp_h, wp_l, b_proj, out, CC);
    }
}